// round 10
// baseline (speedup 1.0000x reference)
#include <cuda_runtime.h>
#include <cuda_fp16.h>
#include <math.h>
#include <stdint.h>

// Problem constants
#define BATCH 2
#define T     2048
#define D     1024
#define NH    16
#define HD    64
#define ROWS  (BATCH * T)        // 4096
#define BHCNT (BATCH * NH)       // 32

// ---------------- scratch (device globals; no allocation allowed) -------------
__device__ __half g_h16   [(size_t)ROWS * D];
__device__ __half g_qkv16 [(size_t)ROWS * 3 * D];
__device__ __half g_attn16[(size_t)ROWS * D];
__device__ float  g_x1    [(size_t)ROWS * D];
__device__ __half g_h216  [(size_t)ROWS * D];
__device__ __half g_ffn16 [(size_t)ROWS * 4 * D];
__device__ __half g_wqkv16[(size_t)3 * D * D];   // [N,K] fp16
__device__ __half g_wfc16 [(size_t)D * D];
__device__ __half g_w116  [(size_t)4 * D * D];
__device__ __half g_w216  [(size_t)4 * D * D];

// ======================= common helpers =======================
__device__ __forceinline__ uint32_t smem_u32(const void* p) {
    uint32_t a;
    asm("{ .reg .u64 t; cvta.to.shared.u64 t, %1; cvt.u32.u64 %0, t; }" : "=r"(a) : "l"(p));
    return a;
}
__device__ __forceinline__ void cp_async16(uint32_t s, const void* g) {
    asm volatile("cp.async.ca.shared.global [%0], [%1], 16;" :: "r"(s), "l"(g));
}
__device__ __forceinline__ void cp_commit() {
    asm volatile("cp.async.commit_group;" ::: "memory");
}
template<int N>
__device__ __forceinline__ void cp_wait() {
    asm volatile("cp.async.wait_group %0;" :: "n"(N) : "memory");
}
__device__ __forceinline__ void mma_f16(float* c, const uint32_t* a, const uint32_t* b) {
    asm volatile(
        "mma.sync.aligned.m16n8k16.row.col.f32.f16.f16.f32 "
        "{%0,%1,%2,%3}, {%4,%5,%6,%7}, {%8,%9}, {%0,%1,%2,%3};"
        : "+f"(c[0]), "+f"(c[1]), "+f"(c[2]), "+f"(c[3])
        : "r"(a[0]), "r"(a[1]), "r"(a[2]), "r"(a[3]), "r"(b[0]), "r"(b[1]));
}
__device__ __forceinline__ void ldsm_x4(
    uint32_t& r0, uint32_t& r1, uint32_t& r2, uint32_t& r3, uint32_t addr) {
    asm volatile("ldmatrix.sync.aligned.m8n8.x4.shared.b16 {%0,%1,%2,%3}, [%4];"
        : "=r"(r0), "=r"(r1), "=r"(r2), "=r"(r3) : "r"(addr));
}
__device__ __forceinline__ void ldsm_x4_trans(
    uint32_t& r0, uint32_t& r1, uint32_t& r2, uint32_t& r3, uint32_t addr) {
    asm volatile("ldmatrix.sync.aligned.m8n8.x4.trans.shared.b16 {%0,%1,%2,%3}, [%4];"
        : "=r"(r0), "=r"(r1), "=r"(r2), "=r"(r3) : "r"(addr));
}
__device__ __forceinline__ uint32_t packh2(float a, float b) {
    __half2 h = __floats2half2_rn(a, b);
    return *(uint32_t*)&h;
}

// ======================= fp16 mma GEMM (ldmatrix + 3-stage pipeline) =======================
#define HSTR 72
#define HT_B (128 * HSTR * 2)                // 18432 B per tile
#define HSTG_B (2 * HT_B)                    // A+B stage = 36864
#define GEMM_SMEM (3 * HSTG_B)               // 110592 B

template<bool GELU, bool RES>
__global__ __launch_bounds__(128, 2) void gemm_h(
    const __half* __restrict__ A, const __half* __restrict__ B,
    const float* __restrict__ bias, const float* __restrict__ res,
    float* __restrict__ Cf, __half* __restrict__ Ch, int M, int N, int K)
{
    extern __shared__ char smem[];
    const uint32_t sb = smem_u32(smem);
    int t = threadIdx.x;
    int wid = t >> 5, lane = t & 31;
    int wm = wid >> 1, wn = wid & 1;
    int group = lane >> 2, qd = lane & 3;
    int sub = lane >> 3, lr = lane & 7;
    int m0 = blockIdx.y * 128, n0 = blockIdx.x * 128;

    auto load_chunk = [&](int c) {
        int buf = c % 3;
        uint32_t sa = sb + buf * HSTG_B;
        uint32_t sbB = sa + HT_B;
        const __half* Ag = A + (size_t)m0 * K + c * 64;
        const __half* Bg = B + (size_t)n0 * K + c * 64;
        #pragma unroll
        for (int j = 0; j < 8; j++) {
            int idx = t + j * 128;
            int r = idx >> 3, sg = idx & 7;
            cp_async16(sa  + r * (HSTR * 2) + sg * 16, Ag + (size_t)r * K + sg * 8);
            cp_async16(sbB + r * (HSTR * 2) + sg * 16, Bg + (size_t)r * K + sg * 8);
        }
        cp_commit();
    };

    const uint32_t aOff = (uint32_t)(((wm * 64 + (sub & 1) * 8 + lr) * HSTR + (sub >> 1) * 8) * 2);
    const uint32_t bOff = (uint32_t)(((wn * 64 + (sub >> 1) * 8 + lr) * HSTR + (sub & 1) * 8) * 2);

    float acc[4][8][4] = {};
    int nch = K / 64;

    load_chunk(0);
    if (nch > 1) load_chunk(1);
    for (int c = 0; c < nch; c++) {
        if (c == nch - 1) cp_wait<0>(); else cp_wait<1>();
        __syncthreads();
        if (c + 2 < nch) load_chunk(c + 2);

        uint32_t sA = sb + (c % 3) * HSTG_B;
        uint32_t sB = sA + HT_B;
        #pragma unroll
        for (int ks = 0; ks < 4; ks++) {
            uint32_t af[4][4], bf[8][2];
            #pragma unroll
            for (int mt = 0; mt < 4; mt++)
                ldsm_x4(af[mt][0], af[mt][1], af[mt][2], af[mt][3],
                        sA + aOff + mt * (16 * HSTR * 2) + ks * 32);
            #pragma unroll
            for (int np = 0; np < 4; np++)
                ldsm_x4(bf[2 * np][0], bf[2 * np][1], bf[2 * np + 1][0], bf[2 * np + 1][1],
                        sB + bOff + np * (16 * HSTR * 2) + ks * 32);
            #pragma unroll
            for (int mt = 0; mt < 4; mt++)
                #pragma unroll
                for (int nt = 0; nt < 8; nt++)
                    mma_f16(acc[mt][nt], af[mt], bf[nt]);
        }
        __syncthreads();
    }

    #pragma unroll
    for (int nt = 0; nt < 8; nt++) {
        int n = n0 + wn * 64 + nt * 8 + qd * 2;
        float2 bv = *(const float2*)(bias + n);
        #pragma unroll
        for (int mt = 0; mt < 4; mt++) {
            int m = m0 + wm * 64 + mt * 16 + group;
            float* c4 = acc[mt][nt];
            float2 v0 = make_float2(c4[0] + bv.x, c4[1] + bv.y);
            float2 v1 = make_float2(c4[2] + bv.x, c4[3] + bv.y);
            if (GELU) {
                v0.x *= normcdff(v0.x); v0.y *= normcdff(v0.y);
                v1.x *= normcdff(v1.x); v1.y *= normcdff(v1.y);
            }
            if (RES) {
                float2 r0 = *(const float2*)(res + (size_t)m * N + n);
                float2 r1 = *(const float2*)(res + (size_t)(m + 8) * N + n);
                v0.x += r0.x; v0.y += r0.y; v1.x += r1.x; v1.y += r1.y;
            }
            if (Cf) {
                *(float2*)(Cf + (size_t)m * N + n) = v0;
                *(float2*)(Cf + (size_t)(m + 8) * N + n) = v1;
            }
            if (Ch) {
                *(__half2*)(Ch + (size_t)m * N + n) = __floats2half2_rn(v0.x, v0.y);
                *(__half2*)(Ch + (size_t)(m + 8) * N + n) = __floats2half2_rn(v1.x, v1.y);
            }
        }
    }
}

// ======================= weight convert+transpose: fp32 [K,N] -> fp16 [N,K] ==========
// tile 64 k x 32 n; half2 coalesced writes.
__global__ __launch_bounds__(256) void convert_wT(
    const float* __restrict__ in, __half* __restrict__ out, int K, int N)
{
    __shared__ float tile[64][33];
    int k0 = blockIdx.y * 64, n0 = blockIdx.x * 32;
    int tx = threadIdx.x, ty = threadIdx.y;   // 32 x 8
    #pragma unroll
    for (int i = 0; i < 64; i += 8)
        tile[ty + i][tx] = in[(size_t)(k0 + ty + i) * N + n0 + tx];
    __syncthreads();
    #pragma unroll
    for (int j = 0; j < 4; j++) {
        int n = ty + j * 8;
        __half2 h = __floats2half2_rn(tile[2 * tx][n], tile[2 * tx + 1][n]);
        *(__half2*)(out + (size_t)(n0 + n) * K + k0 + 2 * tx) = h;
    }
}

// ======================= flash attention (fp16 mma, paired q-tiles) =======================
#define FS 72
#define FT_B (64 * FS * 2)                 // 9216 B per tile
#define FA_SMEM_B (5 * FT_B)               // Q + 2K + 2V = 46080 B

__global__ __launch_bounds__(128, 2) void flash_h(
    const __half* __restrict__ qkv, __half* __restrict__ O)
{
    extern __shared__ char sm[];
    const uint32_t sb = smem_u32(sm);
    const uint32_t qB = sb;
    const uint32_t kB[2] = { sb + FT_B, sb + 2 * FT_B };
    const uint32_t vB[2] = { sb + 3 * FT_B, sb + 4 * FT_B };

    int bh = blockIdx.y;
    int b = bh >> 4, h = bh & 15;
    int t = threadIdx.x, w = t >> 5, lane = t & 31, gp = lane >> 2, qd = lane & 3;
    int sub = lane >> 3, lr = lane & 7;

    const uint32_t aOff = (uint32_t)(((w * 16 + (sub & 1) * 8 + lr) * FS + (sub >> 1) * 8) * 2);
    const uint32_t kOff = (uint32_t)((((sub >> 1) * 8 + lr) * FS + (sub & 1) * 8) * 2);

    auto load_kv = [&](int kt, int bf) {
        const __half* kg = qkv + (size_t)(b * T + kt * 64) * (3 * D) + D + h * HD;
        #pragma unroll
        for (int i = 0; i < 4; i++) {
            int idx = t + i * 128;
            int row = idx >> 3, sg = idx & 7;
            const __half* kr = kg + (size_t)row * (3 * D) + sg * 8;
            cp_async16(kB[bf] + row * (FS * 2) + sg * 16, kr);
            cp_async16(vB[bf] + row * (FS * 2) + sg * 16, kr + D);
        }
        cp_commit();
    };

    // paired q-tiles: work per CTA = (i+1) + (32-i) = 33 k-tiles, uniform
    int qts[2] = { (int)blockIdx.x, 31 - (int)blockIdx.x };

    for (int ph = 0; ph < 2; ph++) {
        int qt = qts[ph];
        int q0 = qt * 64;

        // stage Q
        {
            const __half* qg = qkv + (size_t)(b * T + q0) * (3 * D) + h * HD;
            #pragma unroll
            for (int i = 0; i < 4; i++) {
                int idx = t + i * 128;
                int row = idx >> 3, sg = idx & 7;
                cp_async16(qB + row * (FS * 2) + sg * 16, qg + (size_t)row * (3 * D) + sg * 8);
            }
            cp_commit();
        }
        load_kv(0, 0);
        cp_wait<1>();      // Q done, kv0 in flight
        __syncthreads();

        uint32_t qf[4][4];
        #pragma unroll
        for (int ks = 0; ks < 4; ks++)
            ldsm_x4(qf[ks][0], qf[ks][1], qf[ks][2], qf[ks][3], qB + aOff + ks * 32);

        float m0 = -INFINITY, m1 = -INFINITY, l0 = 0.f, l1 = 0.f;
        float o[8][4] = {};

        for (int kt = 0; kt <= qt; kt++) {
            int bf = kt & 1;
            if (kt < qt) { load_kv(kt + 1, bf ^ 1); cp_wait<1>(); }
            else         { cp_wait<0>(); }
            __syncthreads();

            // S = Q @ K^T
            float s[8][4] = {};
            #pragma unroll
            for (int ks = 0; ks < 4; ks++) {
                uint32_t bfr[8][2];
                #pragma unroll
                for (int np = 0; np < 4; np++)
                    ldsm_x4(bfr[2 * np][0], bfr[2 * np][1], bfr[2 * np + 1][0], bfr[2 * np + 1][1],
                            kB[bf] + kOff + np * (16 * FS * 2) + ks * 32);
                #pragma unroll
                for (int nt = 0; nt < 8; nt++)
                    mma_f16(s[nt], qf[ks], bfr[nt]);
            }
            bool diag = (kt == qt);
            int r0l = w * 16 + gp;
            #pragma unroll
            for (int nt = 0; nt < 8; nt++) {
                int c = nt * 8 + 2 * qd;
                s[nt][0] *= 0.125f; s[nt][1] *= 0.125f;
                s[nt][2] *= 0.125f; s[nt][3] *= 0.125f;
                if (diag) {
                    if (c     > r0l)     s[nt][0] = -INFINITY;
                    if (c + 1 > r0l)     s[nt][1] = -INFINITY;
                    if (c     > r0l + 8) s[nt][2] = -INFINITY;
                    if (c + 1 > r0l + 8) s[nt][3] = -INFINITY;
                }
            }
            float mx0 = -INFINITY, mx1 = -INFINITY;
            #pragma unroll
            for (int nt = 0; nt < 8; nt++) {
                mx0 = fmaxf(mx0, fmaxf(s[nt][0], s[nt][1]));
                mx1 = fmaxf(mx1, fmaxf(s[nt][2], s[nt][3]));
            }
            mx0 = fmaxf(mx0, __shfl_xor_sync(~0u, mx0, 1));
            mx0 = fmaxf(mx0, __shfl_xor_sync(~0u, mx0, 2));
            mx1 = fmaxf(mx1, __shfl_xor_sync(~0u, mx1, 1));
            mx1 = fmaxf(mx1, __shfl_xor_sync(~0u, mx1, 2));
            float mn0 = fmaxf(m0, mx0), mn1 = fmaxf(m1, mx1);
            float sc0 = __expf(m0 - mn0), sc1 = __expf(m1 - mn1);
            m0 = mn0; m1 = mn1;
            uint32_t pa[8], pb[8];
            float ls0 = 0.f, ls1 = 0.f;
            #pragma unroll
            for (int nt = 0; nt < 8; nt++) {
                float p0 = __expf(s[nt][0] - mn0), p1 = __expf(s[nt][1] - mn0);
                float p2 = __expf(s[nt][2] - mn1), p3 = __expf(s[nt][3] - mn1);
                ls0 += p0 + p1; ls1 += p2 + p3;
                pa[nt] = packh2(p0, p1);
                pb[nt] = packh2(p2, p3);
            }
            ls0 += __shfl_xor_sync(~0u, ls0, 1); ls0 += __shfl_xor_sync(~0u, ls0, 2);
            ls1 += __shfl_xor_sync(~0u, ls1, 1); ls1 += __shfl_xor_sync(~0u, ls1, 2);
            l0 = l0 * sc0 + ls0; l1 = l1 * sc1 + ls1;
            #pragma unroll
            for (int nt = 0; nt < 8; nt++) {
                o[nt][0] *= sc0; o[nt][1] *= sc0; o[nt][2] *= sc1; o[nt][3] *= sc1;
            }
            // O += P @ V
            #pragma unroll
            for (int ks = 0; ks < 4; ks++) {
                uint32_t af[4] = { pa[2 * ks], pb[2 * ks], pa[2 * ks + 1], pb[2 * ks + 1] };
                #pragma unroll
                for (int np = 0; np < 4; np++) {
                    int vrow = ks * 16 + (sub & 1) * 8 + lr;
                    int vcol = np * 16 + (sub >> 1) * 8;
                    uint32_t addr = vB[bf] + (vrow * FS + vcol) * 2;
                    uint32_t b0, b1, b2, b3;
                    ldsm_x4_trans(b0, b1, b2, b3, addr);
                    uint32_t bf0[2] = { b0, b1 }, bf1[2] = { b2, b3 };
                    mma_f16(o[2 * np], af, bf0);
                    mma_f16(o[2 * np + 1], af, bf1);
                }
            }
            __syncthreads();
        }

        float inv0 = 1.f / l0, inv1 = 1.f / l1;
        int r0 = q0 + w * 16 + gp;
        __half* O0 = O + (size_t)(b * T + r0) * D + h * HD;
        __half* O1 = O0 + (size_t)8 * D;
        #pragma unroll
        for (int nt = 0; nt < 8; nt++) {
            int c = nt * 8 + 2 * qd;
            *(__half2*)(O0 + c) = __floats2half2_rn(o[nt][0] * inv0, o[nt][1] * inv0);
            *(__half2*)(O1 + c) = __floats2half2_rn(o[nt][2] * inv1, o[nt][3] * inv1);
        }
    }
}

// ======================= LayerNorm (fp32 in, fp16 out) =======================
__device__ __forceinline__ float block_sum256(float v, float* red) {
    int t = threadIdx.x;
    #pragma unroll
    for (int o = 16; o > 0; o >>= 1) v += __shfl_xor_sync(0xffffffffu, v, o);
    if ((t & 31) == 0) red[t >> 5] = v;
    __syncthreads();
    if (t < 32) {
        float s = (t < 8) ? red[t] : 0.0f;
        #pragma unroll
        for (int o = 4; o > 0; o >>= 1) s += __shfl_xor_sync(0xffffffffu, s, o);
        if (t == 0) red[0] = s;
    }
    __syncthreads();
    float r = red[0];
    __syncthreads();
    return r;
}

__global__ __launch_bounds__(256) void ln_kernel(
    const float* __restrict__ x, const float* __restrict__ g,
    const float* __restrict__ b, __half* __restrict__ out)
{
    __shared__ float red[32];
    int r = blockIdx.x, t = threadIdx.x;
    const float* xr = x + (size_t)r * D;
    float4 v = *(const float4*)(xr + t * 4);
    float mu = block_sum256(v.x + v.y + v.z + v.w, red) * (1.0f / D);
    float dx = v.x - mu, dy = v.y - mu, dz = v.z - mu, dw = v.w - mu;
    float var = block_sum256(dx * dx + dy * dy + dz * dz + dw * dw, red) * (1.0f / D);
    float inv = rsqrtf(var + 1e-5f);
    float4 gv = *(const float4*)(g + t * 4);
    float4 bv = *(const float4*)(b + t * 4);
    __half2 o01 = __floats2half2_rn(dx * inv * gv.x + bv.x, dy * inv * gv.y + bv.y);
    __half2 o23 = __floats2half2_rn(dz * inv * gv.z + bv.z, dw * inv * gv.w + bv.w);
    uint2 pk = make_uint2(*(uint32_t*)&o01, *(uint32_t*)&o23);
    *(uint2*)(out + (size_t)r * D + t * 4) = pk;
}

// ======================= launch =======================
template<typename Tp>
static Tp* sym_addr(const void* sym) {
    void* p = nullptr;
    cudaGetSymbolAddress(&p, sym);
    return (Tp*)p;
}

extern "C" void kernel_launch(void* const* d_in, const int* in_sizes, int n_in,
                              void* d_out, int out_size)
{
    const float* x     = (const float*)d_in[0];
    const float* w_qkv = (const float*)d_in[1];
    const float* b_qkv = (const float*)d_in[2];
    const float* w_fc  = (const float*)d_in[3];
    const float* b_fc  = (const float*)d_in[4];
    const float* ln1_g = (const float*)d_in[5];
    const float* ln1_b = (const float*)d_in[6];
    const float* ln2_g = (const float*)d_in[7];
    const float* ln2_b = (const float*)d_in[8];
    const float* w1    = (const float*)d_in[9];
    const float* b1    = (const float*)d_in[10];
    const float* w2    = (const float*)d_in[11];
    const float* b2    = (const float*)d_in[12];
    float* out = (float*)d_out;

    __half* p_h16  = sym_addr<__half>(g_h16);
    __half* p_qkv  = sym_addr<__half>(g_qkv16);
    __half* p_attn = sym_addr<__half>(g_attn16);
    float*  p_x1   = sym_addr<float>(g_x1);
    __half* p_h216 = sym_addr<__half>(g_h216);
    __half* p_ffn  = sym_addr<__half>(g_ffn16);
    __half* p_wqkv = sym_addr<__half>(g_wqkv16);
    __half* p_wfc  = sym_addr<__half>(g_wfc16);
    __half* p_w1   = sym_addr<__half>(g_w116);
    __half* p_w2   = sym_addr<__half>(g_w216);

    cudaFuncSetAttribute(gemm_h<false, false>, cudaFuncAttributeMaxDynamicSharedMemorySize, GEMM_SMEM);
    cudaFuncSetAttribute(gemm_h<false, true>,  cudaFuncAttributeMaxDynamicSharedMemorySize, GEMM_SMEM);
    cudaFuncSetAttribute(gemm_h<true,  false>, cudaFuncAttributeMaxDynamicSharedMemorySize, GEMM_SMEM);
    cudaFuncSetAttribute(flash_h, cudaFuncAttributeMaxDynamicSharedMemorySize, FA_SMEM_B);

    // weight convert+transpose: fp32 [K,N] -> fp16 [N,K]
    convert_wT<<<dim3(3 * D / 32, D / 64), dim3(32, 8)>>>(w_qkv, p_wqkv, D, 3 * D);
    convert_wT<<<dim3(D / 32, D / 64),     dim3(32, 8)>>>(w_fc,  p_wfc,  D, D);
    convert_wT<<<dim3(4 * D / 32, D / 64), dim3(32, 8)>>>(w1,    p_w1,   D, 4 * D);
    convert_wT<<<dim3(D / 32, 4 * D / 64), dim3(32, 8)>>>(w2,    p_w2,   4 * D, D);

    // 1. h = LN1(x)  (fp16)
    ln_kernel<<<ROWS, 256>>>(x, ln1_g, ln1_b, p_h16);
    // 2. qkv = h @ w_qkv + b_qkv  (fp16 out)
    gemm_h<false, false><<<dim3(3 * D / 128, ROWS / 128), 128, GEMM_SMEM>>>(
        p_h16, p_wqkv, b_qkv, nullptr, nullptr, p_qkv, ROWS, 3 * D, D);
    // 3. fused attention (fp16 in/out, paired q-tiles)
    flash_h<<<dim3(T / 128, BHCNT), 128, FA_SMEM_B>>>(p_qkv, p_attn);
    // 4. x1 = x + attn @ w_fc + b_fc  (fp32)
    gemm_h<false, true><<<dim3(D / 128, ROWS / 128), 128, GEMM_SMEM>>>(
        p_attn, p_wfc, b_fc, x, p_x1, nullptr, ROWS, D, D);
    // 5. h2 = LN2(x1)  (fp16)
    ln_kernel<<<ROWS, 256>>>(p_x1, ln2_g, ln2_b, p_h216);
    // 6. ffn = gelu(h2 @ w1 + b1)  (fp16)
    gemm_h<true, false><<<dim3(4 * D / 128, ROWS / 128), 128, GEMM_SMEM>>>(
        p_h216, p_w1, b1, nullptr, nullptr, p_ffn, ROWS, 4 * D, D);
    // 7. out = x1 + ffn @ w2 + b2  (fp32)
    gemm_h<false, true><<<dim3(D / 128, ROWS / 128), 128, GEMM_SMEM>>>(
        p_ffn, p_w2, b2, p_x1, out, nullptr, ROWS, D, 4 * D);
}

// round 11
// speedup vs baseline: 1.0180x; 1.0180x over previous
#include <cuda_runtime.h>
#include <cuda_fp16.h>
#include <math.h>
#include <stdint.h>

// Problem constants
#define BATCH 2
#define T     2048
#define D     1024
#define NH    16
#define HD    64
#define ROWS  (BATCH * T)        // 4096
#define BHCNT (BATCH * NH)       // 32

// ---------------- scratch (device globals; no allocation allowed) -------------
__device__ __half g_h16   [(size_t)ROWS * D];
__device__ __half g_qkv16 [(size_t)ROWS * 3 * D];
__device__ __half g_attn16[(size_t)ROWS * D];
__device__ float  g_x1    [(size_t)ROWS * D];
__device__ __half g_h216  [(size_t)ROWS * D];
__device__ __half g_ffn16 [(size_t)ROWS * 4 * D];
__device__ __half g_wqkv16[(size_t)3 * D * D];   // [N,K] fp16
__device__ __half g_wfc16 [(size_t)D * D];
__device__ __half g_w116  [(size_t)4 * D * D];
__device__ __half g_w216  [(size_t)4 * D * D];

// ======================= common helpers =======================
__device__ __forceinline__ uint32_t smem_u32(const void* p) {
    uint32_t a;
    asm("{ .reg .u64 t; cvta.to.shared.u64 t, %1; cvt.u32.u64 %0, t; }" : "=r"(a) : "l"(p));
    return a;
}
__device__ __forceinline__ void cp_async16(uint32_t s, const void* g) {
    asm volatile("cp.async.ca.shared.global [%0], [%1], 16;" :: "r"(s), "l"(g));
}
__device__ __forceinline__ void cp_commit() {
    asm volatile("cp.async.commit_group;" ::: "memory");
}
template<int N>
__device__ __forceinline__ void cp_wait() {
    asm volatile("cp.async.wait_group %0;" :: "n"(N) : "memory");
}
__device__ __forceinline__ void mma_f16(float* c, const uint32_t* a, const uint32_t* b) {
    asm volatile(
        "mma.sync.aligned.m16n8k16.row.col.f32.f16.f16.f32 "
        "{%0,%1,%2,%3}, {%4,%5,%6,%7}, {%8,%9}, {%0,%1,%2,%3};"
        : "+f"(c[0]), "+f"(c[1]), "+f"(c[2]), "+f"(c[3])
        : "r"(a[0]), "r"(a[1]), "r"(a[2]), "r"(a[3]), "r"(b[0]), "r"(b[1]));
}
__device__ __forceinline__ void ldsm_x4(
    uint32_t& r0, uint32_t& r1, uint32_t& r2, uint32_t& r3, uint32_t addr) {
    asm volatile("ldmatrix.sync.aligned.m8n8.x4.shared.b16 {%0,%1,%2,%3}, [%4];"
        : "=r"(r0), "=r"(r1), "=r"(r2), "=r"(r3) : "r"(addr));
}
__device__ __forceinline__ void ldsm_x4_trans(
    uint32_t& r0, uint32_t& r1, uint32_t& r2, uint32_t& r3, uint32_t addr) {
    asm volatile("ldmatrix.sync.aligned.m8n8.x4.trans.shared.b16 {%0,%1,%2,%3}, [%4];"
        : "=r"(r0), "=r"(r1), "=r"(r2), "=r"(r3) : "r"(addr));
}
__device__ __forceinline__ uint32_t packh2(float a, float b) {
    __half2 h = __floats2half2_rn(a, b);
    return *(uint32_t*)&h;
}

// ======================= fp16 mma GEMM (ldmatrix, 2-stage) =======================
#define HSTR 72
#define HT_B (128 * HSTR * 2)
#define HSTG_B (2 * HT_B)
#define GEMM_SMEM (2 * HSTG_B)               // 73728 B -> 2 CTAs/SM

template<bool GELU, bool RES>
__global__ __launch_bounds__(128, 2) void gemm_h(
    const __half* __restrict__ A, const __half* __restrict__ B,
    const float* __restrict__ bias, const float* __restrict__ res,
    float* __restrict__ Cf, __half* __restrict__ Ch, int M, int N, int K)
{
    extern __shared__ char smem[];
    const uint32_t sb = smem_u32(smem);
    int t = threadIdx.x;
    int wid = t >> 5, lane = t & 31;
    int wm = wid >> 1, wn = wid & 1;
    int group = lane >> 2, qd = lane & 3;
    int sub = lane >> 3, lr = lane & 7;
    int m0 = blockIdx.y * 128, n0 = blockIdx.x * 128;

    auto load_chunk = [&](int c, int buf) {
        uint32_t sa = sb + buf * HSTG_B;
        uint32_t sbB = sa + HT_B;
        const __half* Ag = A + (size_t)m0 * K + c * 64;
        const __half* Bg = B + (size_t)n0 * K + c * 64;
        #pragma unroll
        for (int j = 0; j < 8; j++) {
            int idx = t + j * 128;
            int r = idx >> 3, sg = idx & 7;
            cp_async16(sa  + r * (HSTR * 2) + sg * 16, Ag + (size_t)r * K + sg * 8);
            cp_async16(sbB + r * (HSTR * 2) + sg * 16, Bg + (size_t)r * K + sg * 8);
        }
        cp_commit();
    };

    const uint32_t aOff = (uint32_t)(((wm * 64 + (sub & 1) * 8 + lr) * HSTR + (sub >> 1) * 8) * 2);
    const uint32_t bOff = (uint32_t)(((wn * 64 + (sub >> 1) * 8 + lr) * HSTR + (sub & 1) * 8) * 2);

    float acc[4][8][4] = {};
    int nch = K / 64;

    load_chunk(0, 0);
    for (int c = 0; c < nch; c++) {
        if (c + 1 < nch) { load_chunk(c + 1, (c + 1) & 1); cp_wait<1>(); }
        else             { cp_wait<0>(); }
        __syncthreads();

        uint32_t sA = sb + (c & 1) * HSTG_B;
        uint32_t sB = sA + HT_B;
        #pragma unroll
        for (int ks = 0; ks < 4; ks++) {
            uint32_t af[4][4], bf[8][2];
            #pragma unroll
            for (int mt = 0; mt < 4; mt++)
                ldsm_x4(af[mt][0], af[mt][1], af[mt][2], af[mt][3],
                        sA + aOff + mt * (16 * HSTR * 2) + ks * 32);
            #pragma unroll
            for (int np = 0; np < 4; np++)
                ldsm_x4(bf[2 * np][0], bf[2 * np][1], bf[2 * np + 1][0], bf[2 * np + 1][1],
                        sB + bOff + np * (16 * HSTR * 2) + ks * 32);
            #pragma unroll
            for (int mt = 0; mt < 4; mt++)
                #pragma unroll
                for (int nt = 0; nt < 8; nt++)
                    mma_f16(acc[mt][nt], af[mt], bf[nt]);
        }
        __syncthreads();
    }

    #pragma unroll
    for (int nt = 0; nt < 8; nt++) {
        int n = n0 + wn * 64 + nt * 8 + qd * 2;
        float2 bv = *(const float2*)(bias + n);
        #pragma unroll
        for (int mt = 0; mt < 4; mt++) {
            int m = m0 + wm * 64 + mt * 16 + group;
            float* c4 = acc[mt][nt];
            float2 v0 = make_float2(c4[0] + bv.x, c4[1] + bv.y);
            float2 v1 = make_float2(c4[2] + bv.x, c4[3] + bv.y);
            if (GELU) {
                v0.x *= normcdff(v0.x); v0.y *= normcdff(v0.y);
                v1.x *= normcdff(v1.x); v1.y *= normcdff(v1.y);
            }
            if (RES) {
                float2 r0 = *(const float2*)(res + (size_t)m * N + n);
                float2 r1 = *(const float2*)(res + (size_t)(m + 8) * N + n);
                v0.x += r0.x; v0.y += r0.y; v1.x += r1.x; v1.y += r1.y;
            }
            if (Cf) {
                *(float2*)(Cf + (size_t)m * N + n) = v0;
                *(float2*)(Cf + (size_t)(m + 8) * N + n) = v1;
            }
            if (Ch) {
                *(__half2*)(Ch + (size_t)m * N + n) = __floats2half2_rn(v0.x, v0.y);
                *(__half2*)(Ch + (size_t)(m + 8) * N + n) = __floats2half2_rn(v1.x, v1.y);
            }
        }
    }
}

// ======================= weight convert+transpose: fp32 [K,N] -> fp16 [N,K] ==========
// tile 64 k x 32 n; half2 coalesced writes.
__global__ __launch_bounds__(256) void convert_wT(
    const float* __restrict__ in, __half* __restrict__ out, int K, int N)
{
    __shared__ float tile[64][33];
    int k0 = blockIdx.y * 64, n0 = blockIdx.x * 32;
    int tx = threadIdx.x, ty = threadIdx.y;   // 32 x 8
    #pragma unroll
    for (int i = 0; i < 64; i += 8)
        tile[ty + i][tx] = in[(size_t)(k0 + ty + i) * N + n0 + tx];
    __syncthreads();
    #pragma unroll
    for (int j = 0; j < 4; j++) {
        int n = ty + j * 8;
        __half2 h = __floats2half2_rn(tile[2 * tx][n], tile[2 * tx + 1][n]);
        *(__half2*)(out + (size_t)(n0 + n) * K + k0 + 2 * tx) = h;
    }
}

// ======================= flash attention (fp16 mma, ldmatrix) =======================
#define FS 72
#define FT_B (64 * FS * 2)                 // 9216 B per tile
#define FA_SMEM_B (5 * FT_B)               // Q + 2K + 2V = 46080 B

__global__ __launch_bounds__(128, 2) void flash_h(
    const __half* __restrict__ qkv, __half* __restrict__ O)
{
    extern __shared__ char sm[];
    const uint32_t sb = smem_u32(sm);
    const uint32_t qB = sb;
    const uint32_t kB[2] = { sb + FT_B, sb + 2 * FT_B };
    const uint32_t vB[2] = { sb + 3 * FT_B, sb + 4 * FT_B };

    int qt = blockIdx.x, bh = blockIdx.y;
    int b = bh >> 4, h = bh & 15;
    int q0 = qt * 64;
    int t = threadIdx.x, w = t >> 5, lane = t & 31, gp = lane >> 2, qd = lane & 3;
    int sub = lane >> 3, lr = lane & 7;

    // stage Q
    {
        const __half* qg = qkv + (size_t)(b * T + q0) * (3 * D) + h * HD;
        #pragma unroll
        for (int i = 0; i < 4; i++) {
            int idx = t + i * 128;
            int row = idx >> 3, sg = idx & 7;
            cp_async16(qB + row * (FS * 2) + sg * 16, qg + (size_t)row * (3 * D) + sg * 8);
        }
        cp_commit();
    }

    auto load_kv = [&](int kt, int bf) {
        const __half* kg = qkv + (size_t)(b * T + kt * 64) * (3 * D) + D + h * HD;
        #pragma unroll
        for (int i = 0; i < 4; i++) {
            int idx = t + i * 128;
            int row = idx >> 3, sg = idx & 7;
            const __half* kr = kg + (size_t)row * (3 * D) + sg * 8;
            cp_async16(kB[bf] + row * (FS * 2) + sg * 16, kr);
            cp_async16(vB[bf] + row * (FS * 2) + sg * 16, kr + D);
        }
        cp_commit();
    };

    load_kv(0, 0);
    cp_wait<1>();
    __syncthreads();

    // Q fragments via ldmatrix (A layout)
    const uint32_t aOff = (uint32_t)(((w * 16 + (sub & 1) * 8 + lr) * FS + (sub >> 1) * 8) * 2);
    uint32_t qf[4][4];
    #pragma unroll
    for (int ks = 0; ks < 4; ks++)
        ldsm_x4(qf[ks][0], qf[ks][1], qf[ks][2], qf[ks][3], qB + aOff + ks * 32);

    // K fragment base (B layout)
    const uint32_t kOff = (uint32_t)((((sub >> 1) * 8 + lr) * FS + (sub & 1) * 8) * 2);

    float m0 = -INFINITY, m1 = -INFINITY, l0 = 0.f, l1 = 0.f;
    float o[8][4] = {};

    for (int kt = 0; kt <= qt; kt++) {
        int bf = kt & 1;
        if (kt < qt) { load_kv(kt + 1, bf ^ 1); cp_wait<1>(); }
        else         { cp_wait<0>(); }
        __syncthreads();

        // S = Q @ K^T
        float s[8][4] = {};
        #pragma unroll
        for (int ks = 0; ks < 4; ks++) {
            uint32_t bfr[8][2];
            #pragma unroll
            for (int np = 0; np < 4; np++)
                ldsm_x4(bfr[2 * np][0], bfr[2 * np][1], bfr[2 * np + 1][0], bfr[2 * np + 1][1],
                        kB[bf] + kOff + np * (16 * FS * 2) + ks * 32);
            #pragma unroll
            for (int nt = 0; nt < 8; nt++)
                mma_f16(s[nt], qf[ks], bfr[nt]);
        }
        // scale + causal mask
        bool diag = (kt == qt);
        int r0l = w * 16 + gp;
        #pragma unroll
        for (int nt = 0; nt < 8; nt++) {
            int c = nt * 8 + 2 * qd;
            s[nt][0] *= 0.125f; s[nt][1] *= 0.125f;
            s[nt][2] *= 0.125f; s[nt][3] *= 0.125f;
            if (diag) {
                if (c     > r0l)     s[nt][0] = -INFINITY;
                if (c + 1 > r0l)     s[nt][1] = -INFINITY;
                if (c     > r0l + 8) s[nt][2] = -INFINITY;
                if (c + 1 > r0l + 8) s[nt][3] = -INFINITY;
            }
        }
        // online softmax
        float mx0 = -INFINITY, mx1 = -INFINITY;
        #pragma unroll
        for (int nt = 0; nt < 8; nt++) {
            mx0 = fmaxf(mx0, fmaxf(s[nt][0], s[nt][1]));
            mx1 = fmaxf(mx1, fmaxf(s[nt][2], s[nt][3]));
        }
        mx0 = fmaxf(mx0, __shfl_xor_sync(~0u, mx0, 1));
        mx0 = fmaxf(mx0, __shfl_xor_sync(~0u, mx0, 2));
        mx1 = fmaxf(mx1, __shfl_xor_sync(~0u, mx1, 1));
        mx1 = fmaxf(mx1, __shfl_xor_sync(~0u, mx1, 2));
        float mn0 = fmaxf(m0, mx0), mn1 = fmaxf(m1, mx1);
        float sc0 = __expf(m0 - mn0), sc1 = __expf(m1 - mn1);
        m0 = mn0; m1 = mn1;
        uint32_t pa[8], pb[8];
        float ls0 = 0.f, ls1 = 0.f;
        #pragma unroll
        for (int nt = 0; nt < 8; nt++) {
            float p0 = __expf(s[nt][0] - mn0), p1 = __expf(s[nt][1] - mn0);
            float p2 = __expf(s[nt][2] - mn1), p3 = __expf(s[nt][3] - mn1);
            ls0 += p0 + p1; ls1 += p2 + p3;
            pa[nt] = packh2(p0, p1);
            pb[nt] = packh2(p2, p3);
        }
        ls0 += __shfl_xor_sync(~0u, ls0, 1); ls0 += __shfl_xor_sync(~0u, ls0, 2);
        ls1 += __shfl_xor_sync(~0u, ls1, 1); ls1 += __shfl_xor_sync(~0u, ls1, 2);
        l0 = l0 * sc0 + ls0; l1 = l1 * sc1 + ls1;
        #pragma unroll
        for (int nt = 0; nt < 8; nt++) {
            o[nt][0] *= sc0; o[nt][1] *= sc0; o[nt][2] *= sc1; o[nt][3] *= sc1;
        }
        // O += P @ V
        #pragma unroll
        for (int ks = 0; ks < 4; ks++) {
            uint32_t af[4] = { pa[2 * ks], pb[2 * ks], pa[2 * ks + 1], pb[2 * ks + 1] };
            #pragma unroll
            for (int np = 0; np < 4; np++) {
                int vrow = ks * 16 + (sub & 1) * 8 + lr;
                int vcol = np * 16 + (sub >> 1) * 8;
                uint32_t addr = vB[bf] + (vrow * FS + vcol) * 2;
                uint32_t b0, b1, b2, b3;
                ldsm_x4_trans(b0, b1, b2, b3, addr);
                uint32_t bf0[2] = { b0, b1 }, bf1[2] = { b2, b3 };
                mma_f16(o[2 * np], af, bf0);
                mma_f16(o[2 * np + 1], af, bf1);
            }
        }
        __syncthreads();
    }

    float inv0 = 1.f / l0, inv1 = 1.f / l1;
    int r0 = q0 + w * 16 + gp;
    __half* O0 = O + (size_t)(b * T + r0) * D + h * HD;
    __half* O1 = O0 + (size_t)8 * D;
    #pragma unroll
    for (int nt = 0; nt < 8; nt++) {
        int c = nt * 8 + 2 * qd;
        *(__half2*)(O0 + c) = __floats2half2_rn(o[nt][0] * inv0, o[nt][1] * inv0);
        *(__half2*)(O1 + c) = __floats2half2_rn(o[nt][2] * inv1, o[nt][3] * inv1);
    }
}

// ======================= LayerNorm (fp32 in, fp16 out) =======================
__device__ __forceinline__ float block_sum256(float v, float* red) {
    int t = threadIdx.x;
    #pragma unroll
    for (int o = 16; o > 0; o >>= 1) v += __shfl_xor_sync(0xffffffffu, v, o);
    if ((t & 31) == 0) red[t >> 5] = v;
    __syncthreads();
    if (t < 32) {
        float s = (t < 8) ? red[t] : 0.0f;
        #pragma unroll
        for (int o = 4; o > 0; o >>= 1) s += __shfl_xor_sync(0xffffffffu, s, o);
        if (t == 0) red[0] = s;
    }
    __syncthreads();
    float r = red[0];
    __syncthreads();
    return r;
}

__global__ __launch_bounds__(256) void ln_kernel(
    const float* __restrict__ x, const float* __restrict__ g,
    const float* __restrict__ b, __half* __restrict__ out)
{
    __shared__ float red[32];
    int r = blockIdx.x, t = threadIdx.x;
    const float* xr = x + (size_t)r * D;
    float4 v = *(const float4*)(xr + t * 4);
    float mu = block_sum256(v.x + v.y + v.z + v.w, red) * (1.0f / D);
    float dx = v.x - mu, dy = v.y - mu, dz = v.z - mu, dw = v.w - mu;
    float var = block_sum256(dx * dx + dy * dy + dz * dz + dw * dw, red) * (1.0f / D);
    float inv = rsqrtf(var + 1e-5f);
    float4 gv = *(const float4*)(g + t * 4);
    float4 bv = *(const float4*)(b + t * 4);
    __half2 o01 = __floats2half2_rn(dx * inv * gv.x + bv.x, dy * inv * gv.y + bv.y);
    __half2 o23 = __floats2half2_rn(dz * inv * gv.z + bv.z, dw * inv * gv.w + bv.w);
    uint2 pk = make_uint2(*(uint32_t*)&o01, *(uint32_t*)&o23);
    *(uint2*)(out + (size_t)r * D + t * 4) = pk;
}

// ======================= launch =======================
template<typename Tp>
static Tp* sym_addr(const void* sym) {
    void* p = nullptr;
    cudaGetSymbolAddress(&p, sym);
    return (Tp*)p;
}

extern "C" void kernel_launch(void* const* d_in, const int* in_sizes, int n_in,
                              void* d_out, int out_size)
{
    const float* x     = (const float*)d_in[0];
    const float* w_qkv = (const float*)d_in[1];
    const float* b_qkv = (const float*)d_in[2];
    const float* w_fc  = (const float*)d_in[3];
    const float* b_fc  = (const float*)d_in[4];
    const float* ln1_g = (const float*)d_in[5];
    const float* ln1_b = (const float*)d_in[6];
    const float* ln2_g = (const float*)d_in[7];
    const float* ln2_b = (const float*)d_in[8];
    const float* w1    = (const float*)d_in[9];
    const float* b1    = (const float*)d_in[10];
    const float* w2    = (const float*)d_in[11];
    const float* b2    = (const float*)d_in[12];
    float* out = (float*)d_out;

    __half* p_h16  = sym_addr<__half>(g_h16);
    __half* p_qkv  = sym_addr<__half>(g_qkv16);
    __half* p_attn = sym_addr<__half>(g_attn16);
    float*  p_x1   = sym_addr<float>(g_x1);
    __half* p_h216 = sym_addr<__half>(g_h216);
    __half* p_ffn  = sym_addr<__half>(g_ffn16);
    __half* p_wqkv = sym_addr<__half>(g_wqkv16);
    __half* p_wfc  = sym_addr<__half>(g_wfc16);
    __half* p_w1   = sym_addr<__half>(g_w116);
    __half* p_w2   = sym_addr<__half>(g_w216);

    cudaFuncSetAttribute(gemm_h<false, false>, cudaFuncAttributeMaxDynamicSharedMemorySize, GEMM_SMEM);
    cudaFuncSetAttribute(gemm_h<false, true>,  cudaFuncAttributeMaxDynamicSharedMemorySize, GEMM_SMEM);
    cudaFuncSetAttribute(gemm_h<true,  false>, cudaFuncAttributeMaxDynamicSharedMemorySize, GEMM_SMEM);
    cudaFuncSetAttribute(flash_h, cudaFuncAttributeMaxDynamicSharedMemorySize, FA_SMEM_B);
    // maximize smem carveout so 2 CTAs/SM always fit
    cudaFuncSetAttribute(gemm_h<false, false>, cudaFuncAttributePreferredSharedMemoryCarveout, 100);
    cudaFuncSetAttribute(gemm_h<false, true>,  cudaFuncAttributePreferredSharedMemoryCarveout, 100);
    cudaFuncSetAttribute(gemm_h<true,  false>, cudaFuncAttributePreferredSharedMemoryCarveout, 100);
    cudaFuncSetAttribute(flash_h, cudaFuncAttributePreferredSharedMemoryCarveout, 100);

    // weight convert+transpose: fp32 [K,N] -> fp16 [N,K]
    convert_wT<<<dim3(3 * D / 32, D / 64), dim3(32, 8)>>>(w_qkv, p_wqkv, D, 3 * D);
    convert_wT<<<dim3(D / 32, D / 64),     dim3(32, 8)>>>(w_fc,  p_wfc,  D, D);
    convert_wT<<<dim3(4 * D / 32, D / 64), dim3(32, 8)>>>(w1,    p_w1,   D, 4 * D);
    convert_wT<<<dim3(D / 32, 4 * D / 64), dim3(32, 8)>>>(w2,    p_w2,   4 * D, D);

    // 1. h = LN1(x)  (fp16)
    ln_kernel<<<ROWS, 256>>>(x, ln1_g, ln1_b, p_h16);
    // 2. qkv = h @ w_qkv + b_qkv  (fp16 out)
    gemm_h<false, false><<<dim3(3 * D / 128, ROWS / 128), 128, GEMM_SMEM>>>(
        p_h16, p_wqkv, b_qkv, nullptr, nullptr, p_qkv, ROWS, 3 * D, D);
    // 3. fused attention (fp16 in/out)
    flash_h<<<dim3(T / 64, BHCNT), 128, FA_SMEM_B>>>(p_qkv, p_attn);
    // 4. x1 = x + attn @ w_fc + b_fc  (fp32)
    gemm_h<false, true><<<dim3(D / 128, ROWS / 128), 128, GEMM_SMEM>>>(
        p_attn, p_wfc, b_fc, x, p_x1, nullptr, ROWS, D, D);
    // 5. h2 = LN2(x1)  (fp16)
    ln_kernel<<<ROWS, 256>>>(p_x1, ln2_g, ln2_b, p_h216);
    // 6. ffn = gelu(h2 @ w1 + b1)  (fp16)
    gemm_h<true, false><<<dim3(4 * D / 128, ROWS / 128), 128, GEMM_SMEM>>>(
        p_h216, p_w1, b1, nullptr, nullptr, p_ffn, ROWS, 4 * D, D);
    // 7. out = x1 + ffn @ w2 + b2  (fp32)
    gemm_h<false, true><<<dim3(D / 128, ROWS / 128), 128, GEMM_SMEM>>>(
        p_ffn, p_w2, b2, p_x1, out, nullptr, ROWS, D, 4 * D);
}

// round 12
// speedup vs baseline: 1.0990x; 1.0795x over previous
#include <cuda_runtime.h>
#include <cuda_fp16.h>
#include <math.h>
#include <stdint.h>

// Problem constants
#define BATCH 2
#define T     2048
#define D     1024
#define NH    16
#define HD    64
#define ROWS  (BATCH * T)        // 4096
#define BHCNT (BATCH * NH)       // 32

// ---------------- scratch (device globals; no allocation allowed) -------------
__device__ __half g_h16   [(size_t)ROWS * D];
__device__ __half g_qkv16 [(size_t)ROWS * 3 * D];
__device__ __half g_attn16[(size_t)ROWS * D];
__device__ float  g_x1    [(size_t)ROWS * D];
__device__ __half g_h216  [(size_t)ROWS * D];
__device__ __half g_ffn16 [(size_t)ROWS * 4 * D];
__device__ __half g_wqkv16[(size_t)3 * D * D];   // [N,K] fp16
__device__ __half g_wfc16 [(size_t)D * D];
__device__ __half g_w116  [(size_t)4 * D * D];
__device__ __half g_w216  [(size_t)4 * D * D];

// ======================= common helpers =======================
__device__ __forceinline__ uint32_t smem_u32(const void* p) {
    uint32_t a;
    asm("{ .reg .u64 t; cvta.to.shared.u64 t, %1; cvt.u32.u64 %0, t; }" : "=r"(a) : "l"(p));
    return a;
}
__device__ __forceinline__ void cp_async16(uint32_t s, const void* g) {
    asm volatile("cp.async.ca.shared.global [%0], [%1], 16;" :: "r"(s), "l"(g));
}
__device__ __forceinline__ void cp_commit() {
    asm volatile("cp.async.commit_group;" ::: "memory");
}
template<int N>
__device__ __forceinline__ void cp_wait() {
    asm volatile("cp.async.wait_group %0;" :: "n"(N) : "memory");
}
__device__ __forceinline__ void mma_f16(float* c, const uint32_t* a, const uint32_t* b) {
    asm volatile(
        "mma.sync.aligned.m16n8k16.row.col.f32.f16.f16.f32 "
        "{%0,%1,%2,%3}, {%4,%5,%6,%7}, {%8,%9}, {%0,%1,%2,%3};"
        : "+f"(c[0]), "+f"(c[1]), "+f"(c[2]), "+f"(c[3])
        : "r"(a[0]), "r"(a[1]), "r"(a[2]), "r"(a[3]), "r"(b[0]), "r"(b[1]));
}
__device__ __forceinline__ void ldsm_x4(
    uint32_t& r0, uint32_t& r1, uint32_t& r2, uint32_t& r3, uint32_t addr) {
    asm volatile("ldmatrix.sync.aligned.m8n8.x4.shared.b16 {%0,%1,%2,%3}, [%4];"
        : "=r"(r0), "=r"(r1), "=r"(r2), "=r"(r3) : "r"(addr));
}
__device__ __forceinline__ void ldsm_x4_trans(
    uint32_t& r0, uint32_t& r1, uint32_t& r2, uint32_t& r3, uint32_t addr) {
    asm volatile("ldmatrix.sync.aligned.m8n8.x4.trans.shared.b16 {%0,%1,%2,%3}, [%4];"
        : "=r"(r0), "=r"(r1), "=r"(r2), "=r"(r3) : "r"(addr));
}
__device__ __forceinline__ uint32_t packh2(float a, float b) {
    __half2 h = __floats2half2_rn(a, b);
    return *(uint32_t*)&h;
}

// ======================= fp16 mma GEMM (ldmatrix, 2-stage) =======================
#define HSTR 72
#define HT_B (128 * HSTR * 2)
#define HSTG_B (2 * HT_B)
#define GEMM_SMEM (2 * HSTG_B)               // 73728 B -> 2 CTAs/SM

template<bool GELU, bool RES>
__global__ __launch_bounds__(128, 2) void gemm_h(
    const __half* __restrict__ A, const __half* __restrict__ B,
    const float* __restrict__ bias, const float* __restrict__ res,
    float* __restrict__ Cf, __half* __restrict__ Ch, int M, int N, int K)
{
    extern __shared__ char smem[];
    const uint32_t sb = smem_u32(smem);
    int t = threadIdx.x;
    int wid = t >> 5, lane = t & 31;
    int wm = wid >> 1, wn = wid & 1;
    int group = lane >> 2, qd = lane & 3;
    int sub = lane >> 3, lr = lane & 7;
    int m0 = blockIdx.y * 128, n0 = blockIdx.x * 128;

    auto load_chunk = [&](int c, int buf) {
        uint32_t sa = sb + buf * HSTG_B;
        uint32_t sbB = sa + HT_B;
        const __half* Ag = A + (size_t)m0 * K + c * 64;
        const __half* Bg = B + (size_t)n0 * K + c * 64;
        #pragma unroll
        for (int j = 0; j < 8; j++) {
            int idx = t + j * 128;
            int r = idx >> 3, sg = idx & 7;
            cp_async16(sa  + r * (HSTR * 2) + sg * 16, Ag + (size_t)r * K + sg * 8);
            cp_async16(sbB + r * (HSTR * 2) + sg * 16, Bg + (size_t)r * K + sg * 8);
        }
        cp_commit();
    };

    const uint32_t aOff = (uint32_t)(((wm * 64 + (sub & 1) * 8 + lr) * HSTR + (sub >> 1) * 8) * 2);
    const uint32_t bOff = (uint32_t)(((wn * 64 + (sub >> 1) * 8 + lr) * HSTR + (sub & 1) * 8) * 2);

    float acc[4][8][4] = {};
    int nch = K / 64;

    load_chunk(0, 0);
    for (int c = 0; c < nch; c++) {
        if (c + 1 < nch) { load_chunk(c + 1, (c + 1) & 1); cp_wait<1>(); }
        else             { cp_wait<0>(); }
        __syncthreads();

        uint32_t sA = sb + (c & 1) * HSTG_B;
        uint32_t sB = sA + HT_B;
        #pragma unroll
        for (int ks = 0; ks < 4; ks++) {
            uint32_t af[4][4], bf[8][2];
            #pragma unroll
            for (int mt = 0; mt < 4; mt++)
                ldsm_x4(af[mt][0], af[mt][1], af[mt][2], af[mt][3],
                        sA + aOff + mt * (16 * HSTR * 2) + ks * 32);
            #pragma unroll
            for (int np = 0; np < 4; np++)
                ldsm_x4(bf[2 * np][0], bf[2 * np][1], bf[2 * np + 1][0], bf[2 * np + 1][1],
                        sB + bOff + np * (16 * HSTR * 2) + ks * 32);
            #pragma unroll
            for (int mt = 0; mt < 4; mt++)
                #pragma unroll
                for (int nt = 0; nt < 8; nt++)
                    mma_f16(acc[mt][nt], af[mt], bf[nt]);
        }
        __syncthreads();
    }

    #pragma unroll
    for (int nt = 0; nt < 8; nt++) {
        int n = n0 + wn * 64 + nt * 8 + qd * 2;
        float2 bv = *(const float2*)(bias + n);
        #pragma unroll
        for (int mt = 0; mt < 4; mt++) {
            int m = m0 + wm * 64 + mt * 16 + group;
            float* c4 = acc[mt][nt];
            float2 v0 = make_float2(c4[0] + bv.x, c4[1] + bv.y);
            float2 v1 = make_float2(c4[2] + bv.x, c4[3] + bv.y);
            if (GELU) {
                v0.x *= normcdff(v0.x); v0.y *= normcdff(v0.y);
                v1.x *= normcdff(v1.x); v1.y *= normcdff(v1.y);
            }
            if (RES) {
                float2 r0 = *(const float2*)(res + (size_t)m * N + n);
                float2 r1 = *(const float2*)(res + (size_t)(m + 8) * N + n);
                v0.x += r0.x; v0.y += r0.y; v1.x += r1.x; v1.y += r1.y;
            }
            if (Cf) {
                *(float2*)(Cf + (size_t)m * N + n) = v0;
                *(float2*)(Cf + (size_t)(m + 8) * N + n) = v1;
            }
            if (Ch) {
                *(__half2*)(Ch + (size_t)m * N + n) = __floats2half2_rn(v0.x, v0.y);
                *(__half2*)(Ch + (size_t)(m + 8) * N + n) = __floats2half2_rn(v1.x, v1.y);
            }
        }
    }
}

// ======================= weight convert+transpose: fp32 [K,N] -> fp16 [N,K] ==========
// tile 64 k x 32 n; half2 coalesced writes.
__global__ __launch_bounds__(256) void convert_wT(
    const float* __restrict__ in, __half* __restrict__ out, int K, int N)
{
    __shared__ float tile[64][33];
    int k0 = blockIdx.y * 64, n0 = blockIdx.x * 32;
    int tx = threadIdx.x, ty = threadIdx.y;   // 32 x 8
    #pragma unroll
    for (int i = 0; i < 64; i += 8)
        tile[ty + i][tx] = in[(size_t)(k0 + ty + i) * N + n0 + tx];
    __syncthreads();
    #pragma unroll
    for (int j = 0; j < 4; j++) {
        int n = ty + j * 8;
        __half2 h = __floats2half2_rn(tile[2 * tx][n], tile[2 * tx + 1][n]);
        *(__half2*)(out + (size_t)(n0 + n) * K + k0 + 2 * tx) = h;
    }
}

// ======================= flash attention (fp16 mma, ldmatrix) =======================
#define FS 72
#define FT_B (64 * FS * 2)                 // 9216 B per tile
#define FA_SMEM_B (5 * FT_B)               // Q + 2K + 2V = 46080 B

__global__ __launch_bounds__(128, 2) void flash_h(
    const __half* __restrict__ qkv, __half* __restrict__ O)
{
    extern __shared__ char sm[];
    const uint32_t sb = smem_u32(sm);
    const uint32_t qB = sb;
    const uint32_t kB[2] = { sb + FT_B, sb + 2 * FT_B };
    const uint32_t vB[2] = { sb + 3 * FT_B, sb + 4 * FT_B };

    int qt = blockIdx.x, bh = blockIdx.y;
    int b = bh >> 4, h = bh & 15;
    int q0 = qt * 64;
    int t = threadIdx.x, w = t >> 5, lane = t & 31, gp = lane >> 2, qd = lane & 3;
    int sub = lane >> 3, lr = lane & 7;

    // stage Q
    {
        const __half* qg = qkv + (size_t)(b * T + q0) * (3 * D) + h * HD;
        #pragma unroll
        for (int i = 0; i < 4; i++) {
            int idx = t + i * 128;
            int row = idx >> 3, sg = idx & 7;
            cp_async16(qB + row * (FS * 2) + sg * 16, qg + (size_t)row * (3 * D) + sg * 8);
        }
        cp_commit();
    }

    auto load_kv = [&](int kt, int bf) {
        const __half* kg = qkv + (size_t)(b * T + kt * 64) * (3 * D) + D + h * HD;
        #pragma unroll
        for (int i = 0; i < 4; i++) {
            int idx = t + i * 128;
            int row = idx >> 3, sg = idx & 7;
            const __half* kr = kg + (size_t)row * (3 * D) + sg * 8;
            cp_async16(kB[bf] + row * (FS * 2) + sg * 16, kr);
            cp_async16(vB[bf] + row * (FS * 2) + sg * 16, kr + D);
        }
        cp_commit();
    };

    load_kv(0, 0);
    cp_wait<1>();
    __syncthreads();

    // Q fragments via ldmatrix (A layout)
    const uint32_t aOff = (uint32_t)(((w * 16 + (sub & 1) * 8 + lr) * FS + (sub >> 1) * 8) * 2);
    uint32_t qf[4][4];
    #pragma unroll
    for (int ks = 0; ks < 4; ks++)
        ldsm_x4(qf[ks][0], qf[ks][1], qf[ks][2], qf[ks][3], qB + aOff + ks * 32);

    // K fragment base (B layout)
    const uint32_t kOff = (uint32_t)((((sub >> 1) * 8 + lr) * FS + (sub & 1) * 8) * 2);

    float m0 = -INFINITY, m1 = -INFINITY, l0 = 0.f, l1 = 0.f;
    float o[8][4] = {};

    for (int kt = 0; kt <= qt; kt++) {
        int bf = kt & 1;
        if (kt < qt) { load_kv(kt + 1, bf ^ 1); cp_wait<1>(); }
        else         { cp_wait<0>(); }
        __syncthreads();

        // S = Q @ K^T
        float s[8][4] = {};
        #pragma unroll
        for (int ks = 0; ks < 4; ks++) {
            uint32_t bfr[8][2];
            #pragma unroll
            for (int np = 0; np < 4; np++)
                ldsm_x4(bfr[2 * np][0], bfr[2 * np][1], bfr[2 * np + 1][0], bfr[2 * np + 1][1],
                        kB[bf] + kOff + np * (16 * FS * 2) + ks * 32);
            #pragma unroll
            for (int nt = 0; nt < 8; nt++)
                mma_f16(s[nt], qf[ks], bfr[nt]);
        }
        // scale + causal mask
        bool diag = (kt == qt);
        int r0l = w * 16 + gp;
        #pragma unroll
        for (int nt = 0; nt < 8; nt++) {
            int c = nt * 8 + 2 * qd;
            s[nt][0] *= 0.125f; s[nt][1] *= 0.125f;
            s[nt][2] *= 0.125f; s[nt][3] *= 0.125f;
            if (diag) {
                if (c     > r0l)     s[nt][0] = -INFINITY;
                if (c + 1 > r0l)     s[nt][1] = -INFINITY;
                if (c     > r0l + 8) s[nt][2] = -INFINITY;
                if (c + 1 > r0l + 8) s[nt][3] = -INFINITY;
            }
        }
        // online softmax
        float mx0 = -INFINITY, mx1 = -INFINITY;
        #pragma unroll
        for (int nt = 0; nt < 8; nt++) {
            mx0 = fmaxf(mx0, fmaxf(s[nt][0], s[nt][1]));
            mx1 = fmaxf(mx1, fmaxf(s[nt][2], s[nt][3]));
        }
        mx0 = fmaxf(mx0, __shfl_xor_sync(~0u, mx0, 1));
        mx0 = fmaxf(mx0, __shfl_xor_sync(~0u, mx0, 2));
        mx1 = fmaxf(mx1, __shfl_xor_sync(~0u, mx1, 1));
        mx1 = fmaxf(mx1, __shfl_xor_sync(~0u, mx1, 2));
        float mn0 = fmaxf(m0, mx0), mn1 = fmaxf(m1, mx1);
        float sc0 = __expf(m0 - mn0), sc1 = __expf(m1 - mn1);
        m0 = mn0; m1 = mn1;
        uint32_t pa[8], pb[8];
        float ls0 = 0.f, ls1 = 0.f;
        #pragma unroll
        for (int nt = 0; nt < 8; nt++) {
            float p0 = __expf(s[nt][0] - mn0), p1 = __expf(s[nt][1] - mn0);
            float p2 = __expf(s[nt][2] - mn1), p3 = __expf(s[nt][3] - mn1);
            ls0 += p0 + p1; ls1 += p2 + p3;
            pa[nt] = packh2(p0, p1);
            pb[nt] = packh2(p2, p3);
        }
        ls0 += __shfl_xor_sync(~0u, ls0, 1); ls0 += __shfl_xor_sync(~0u, ls0, 2);
        ls1 += __shfl_xor_sync(~0u, ls1, 1); ls1 += __shfl_xor_sync(~0u, ls1, 2);
        l0 = l0 * sc0 + ls0; l1 = l1 * sc1 + ls1;
        #pragma unroll
        for (int nt = 0; nt < 8; nt++) {
            o[nt][0] *= sc0; o[nt][1] *= sc0; o[nt][2] *= sc1; o[nt][3] *= sc1;
        }
        // O += P @ V
        #pragma unroll
        for (int ks = 0; ks < 4; ks++) {
            uint32_t af[4] = { pa[2 * ks], pb[2 * ks], pa[2 * ks + 1], pb[2 * ks + 1] };
            #pragma unroll
            for (int np = 0; np < 4; np++) {
                int vrow = ks * 16 + (sub & 1) * 8 + lr;
                int vcol = np * 16 + (sub >> 1) * 8;
                uint32_t addr = vB[bf] + (vrow * FS + vcol) * 2;
                uint32_t b0, b1, b2, b3;
                ldsm_x4_trans(b0, b1, b2, b3, addr);
                uint32_t bf0[2] = { b0, b1 }, bf1[2] = { b2, b3 };
                mma_f16(o[2 * np], af, bf0);
                mma_f16(o[2 * np + 1], af, bf1);
            }
        }
        __syncthreads();
    }

    float inv0 = 1.f / l0, inv1 = 1.f / l1;
    int r0 = q0 + w * 16 + gp;
    __half* O0 = O + (size_t)(b * T + r0) * D + h * HD;
    __half* O1 = O0 + (size_t)8 * D;
    #pragma unroll
    for (int nt = 0; nt < 8; nt++) {
        int c = nt * 8 + 2 * qd;
        *(__half2*)(O0 + c) = __floats2half2_rn(o[nt][0] * inv0, o[nt][1] * inv0);
        *(__half2*)(O1 + c) = __floats2half2_rn(o[nt][2] * inv1, o[nt][3] * inv1);
    }
}

// ======================= LayerNorm (fp32 in, fp16 out) =======================
__device__ __forceinline__ float block_sum256(float v, float* red) {
    int t = threadIdx.x;
    #pragma unroll
    for (int o = 16; o > 0; o >>= 1) v += __shfl_xor_sync(0xffffffffu, v, o);
    if ((t & 31) == 0) red[t >> 5] = v;
    __syncthreads();
    if (t < 32) {
        float s = (t < 8) ? red[t] : 0.0f;
        #pragma unroll
        for (int o = 4; o > 0; o >>= 1) s += __shfl_xor_sync(0xffffffffu, s, o);
        if (t == 0) red[0] = s;
    }
    __syncthreads();
    float r = red[0];
    __syncthreads();
    return r;
}

__global__ __launch_bounds__(256) void ln_kernel(
    const float* __restrict__ x, const float* __restrict__ g,
    const float* __restrict__ b, __half* __restrict__ out)
{
    __shared__ float red[32];
    int r = blockIdx.x, t = threadIdx.x;
    const float* xr = x + (size_t)r * D;
    float4 v = *(const float4*)(xr + t * 4);
    float mu = block_sum256(v.x + v.y + v.z + v.w, red) * (1.0f / D);
    float dx = v.x - mu, dy = v.y - mu, dz = v.z - mu, dw = v.w - mu;
    float var = block_sum256(dx * dx + dy * dy + dz * dz + dw * dw, red) * (1.0f / D);
    float inv = rsqrtf(var + 1e-5f);
    float4 gv = *(const float4*)(g + t * 4);
    float4 bv = *(const float4*)(b + t * 4);
    __half2 o01 = __floats2half2_rn(dx * inv * gv.x + bv.x, dy * inv * gv.y + bv.y);
    __half2 o23 = __floats2half2_rn(dz * inv * gv.z + bv.z, dw * inv * gv.w + bv.w);
    uint2 pk = make_uint2(*(uint32_t*)&o01, *(uint32_t*)&o23);
    *(uint2*)(out + (size_t)r * D + t * 4) = pk;
}

// ======================= launch =======================
template<typename Tp>
static Tp* sym_addr(const void* sym) {
    void* p = nullptr;
    cudaGetSymbolAddress(&p, sym);
    return (Tp*)p;
}

extern "C" void kernel_launch(void* const* d_in, const int* in_sizes, int n_in,
                              void* d_out, int out_size)
{
    const float* x     = (const float*)d_in[0];
    const float* w_qkv = (const float*)d_in[1];
    const float* b_qkv = (const float*)d_in[2];
    const float* w_fc  = (const float*)d_in[3];
    const float* b_fc  = (const float*)d_in[4];
    const float* ln1_g = (const float*)d_in[5];
    const float* ln1_b = (const float*)d_in[6];
    const float* ln2_g = (const float*)d_in[7];
    const float* ln2_b = (const float*)d_in[8];
    const float* w1    = (const float*)d_in[9];
    const float* b1    = (const float*)d_in[10];
    const float* w2    = (const float*)d_in[11];
    const float* b2    = (const float*)d_in[12];
    float* out = (float*)d_out;

    __half* p_h16  = sym_addr<__half>(g_h16);
    __half* p_qkv  = sym_addr<__half>(g_qkv16);
    __half* p_attn = sym_addr<__half>(g_attn16);
    float*  p_x1   = sym_addr<float>(g_x1);
    __half* p_h216 = sym_addr<__half>(g_h216);
    __half* p_ffn  = sym_addr<__half>(g_ffn16);
    __half* p_wqkv = sym_addr<__half>(g_wqkv16);
    __half* p_wfc  = sym_addr<__half>(g_wfc16);
    __half* p_w1   = sym_addr<__half>(g_w116);
    __half* p_w2   = sym_addr<__half>(g_w216);

    cudaFuncSetAttribute(gemm_h<false, false>, cudaFuncAttributeMaxDynamicSharedMemorySize, GEMM_SMEM);
    cudaFuncSetAttribute(gemm_h<false, true>,  cudaFuncAttributeMaxDynamicSharedMemorySize, GEMM_SMEM);
    cudaFuncSetAttribute(gemm_h<true,  false>, cudaFuncAttributeMaxDynamicSharedMemorySize, GEMM_SMEM);
    cudaFuncSetAttribute(flash_h, cudaFuncAttributeMaxDynamicSharedMemorySize, FA_SMEM_B);

    // weight convert+transpose: fp32 [K,N] -> fp16 [N,K]
    convert_wT<<<dim3(3 * D / 32, D / 64), dim3(32, 8)>>>(w_qkv, p_wqkv, D, 3 * D);
    convert_wT<<<dim3(D / 32, D / 64),     dim3(32, 8)>>>(w_fc,  p_wfc,  D, D);
    convert_wT<<<dim3(4 * D / 32, D / 64), dim3(32, 8)>>>(w1,    p_w1,   D, 4 * D);
    convert_wT<<<dim3(D / 32, 4 * D / 64), dim3(32, 8)>>>(w2,    p_w2,   4 * D, D);

    // 1. h = LN1(x)  (fp16)
    ln_kernel<<<ROWS, 256>>>(x, ln1_g, ln1_b, p_h16);
    // 2. qkv = h @ w_qkv + b_qkv  (fp16 out)
    gemm_h<false, false><<<dim3(3 * D / 128, ROWS / 128), 128, GEMM_SMEM>>>(
        p_h16, p_wqkv, b_qkv, nullptr, nullptr, p_qkv, ROWS, 3 * D, D);
    // 3. fused attention (fp16 in/out)
    flash_h<<<dim3(T / 64, BHCNT), 128, FA_SMEM_B>>>(p_qkv, p_attn);
    // 4. x1 = x + attn @ w_fc + b_fc  (fp32)
    gemm_h<false, true><<<dim3(D / 128, ROWS / 128), 128, GEMM_SMEM>>>(
        p_attn, p_wfc, b_fc, x, p_x1, nullptr, ROWS, D, D);
    // 5. h2 = LN2(x1)  (fp16)
    ln_kernel<<<ROWS, 256>>>(p_x1, ln2_g, ln2_b, p_h216);
    // 6. ffn = gelu(h2 @ w1 + b1)  (fp16)
    gemm_h<true, false><<<dim3(4 * D / 128, ROWS / 128), 128, GEMM_SMEM>>>(
        p_h216, p_w1, b1, nullptr, nullptr, p_ffn, ROWS, 4 * D, D);
    // 7. out = x1 + ffn @ w2 + b2  (fp32)
    gemm_h<false, true><<<dim3(D / 128, ROWS / 128), 128, GEMM_SMEM>>>(
        p_ffn, p_w2, b2, p_x1, out, nullptr, ROWS, D, 4 * D);
}

// round 13
// speedup vs baseline: 1.2134x; 1.1042x over previous
#include <cuda_runtime.h>
#include <cuda_fp16.h>
#include <math.h>
#include <stdint.h>

// Problem constants
#define BATCH 2
#define T     2048
#define D     1024
#define NH    16
#define HD    64
#define ROWS  (BATCH * T)        // 4096
#define BHCNT (BATCH * NH)       // 32

// ---------------- scratch (device globals; no allocation allowed) -------------
__device__ __half g_h16   [(size_t)ROWS * D];
__device__ __half g_qkv16 [(size_t)ROWS * 3 * D];
__device__ __half g_attn16[(size_t)ROWS * D];
__device__ float  g_x1    [(size_t)ROWS * D];
__device__ __half g_h216  [(size_t)ROWS * D];
__device__ __half g_ffn16 [(size_t)ROWS * 4 * D];
__device__ __half g_wqkv16[(size_t)3 * D * D];   // [N,K] fp16
__device__ __half g_wfc16 [(size_t)D * D];
__device__ __half g_w116  [(size_t)4 * D * D];
__device__ __half g_w216  [(size_t)4 * D * D];

// ======================= common helpers =======================
__device__ __forceinline__ uint32_t smem_u32(const void* p) {
    uint32_t a;
    asm("{ .reg .u64 t; cvta.to.shared.u64 t, %1; cvt.u32.u64 %0, t; }" : "=r"(a) : "l"(p));
    return a;
}
__device__ __forceinline__ void cp_async16(uint32_t s, const void* g) {
    asm volatile("cp.async.ca.shared.global [%0], [%1], 16;" :: "r"(s), "l"(g));
}
__device__ __forceinline__ void cp_commit() {
    asm volatile("cp.async.commit_group;" ::: "memory");
}
template<int N>
__device__ __forceinline__ void cp_wait() {
    asm volatile("cp.async.wait_group %0;" :: "n"(N) : "memory");
}
__device__ __forceinline__ void mma_f16(float* c, const uint32_t* a, const uint32_t* b) {
    asm volatile(
        "mma.sync.aligned.m16n8k16.row.col.f32.f16.f16.f32 "
        "{%0,%1,%2,%3}, {%4,%5,%6,%7}, {%8,%9}, {%0,%1,%2,%3};"
        : "+f"(c[0]), "+f"(c[1]), "+f"(c[2]), "+f"(c[3])
        : "r"(a[0]), "r"(a[1]), "r"(a[2]), "r"(a[3]), "r"(b[0]), "r"(b[1]));
}
__device__ __forceinline__ void ldsm_x4(
    uint32_t& r0, uint32_t& r1, uint32_t& r2, uint32_t& r3, uint32_t addr) {
    asm volatile("ldmatrix.sync.aligned.m8n8.x4.shared.b16 {%0,%1,%2,%3}, [%4];"
        : "=r"(r0), "=r"(r1), "=r"(r2), "=r"(r3) : "r"(addr));
}
__device__ __forceinline__ void ldsm_x4_trans(
    uint32_t& r0, uint32_t& r1, uint32_t& r2, uint32_t& r3, uint32_t addr) {
    asm volatile("ldmatrix.sync.aligned.m8n8.x4.trans.shared.b16 {%0,%1,%2,%3}, [%4];"
        : "=r"(r0), "=r"(r1), "=r"(r2), "=r"(r3) : "r"(addr));
}
__device__ __forceinline__ uint32_t packh2(float a, float b) {
    __half2 h = __floats2half2_rn(a, b);
    return *(uint32_t*)&h;
}

// ======================= fp16 mma GEMM (256 thr, 8 warps, ldmatrix, 2-stage) ==========
#define HSTR 72
#define HT_B (128 * HSTR * 2)
#define HSTG_B (2 * HT_B)
#define GEMM_SMEM (2 * HSTG_B)               // 73728 B -> 2 CTAs/SM (16 warps/SM)

template<bool GELU, bool RES>
__global__ __launch_bounds__(256, 2) void gemm_h(
    const __half* __restrict__ A, const __half* __restrict__ B,
    const float* __restrict__ bias, const float* __restrict__ res,
    float* __restrict__ Cf, __half* __restrict__ Ch, int M, int N, int K)
{
    extern __shared__ char smem[];
    const uint32_t sb = smem_u32(smem);
    int t = threadIdx.x;
    int wid = t >> 5, lane = t & 31;
    int wm = wid >> 2, wn = wid & 3;              // 2x4 warp grid, warp tile 64x32
    int group = lane >> 2, qd = lane & 3;
    int sub = lane >> 3, lr = lane & 7;
    int m0 = blockIdx.y * 128, n0 = blockIdx.x * 128;

    auto load_chunk = [&](int c, int buf) {
        uint32_t sa = sb + buf * HSTG_B;
        uint32_t sbB = sa + HT_B;
        const __half* Ag = A + (size_t)m0 * K + c * 64;
        const __half* Bg = B + (size_t)n0 * K + c * 64;
        #pragma unroll
        for (int j = 0; j < 4; j++) {
            int idx = t + j * 256;
            int r = idx >> 3, sg = idx & 7;
            cp_async16(sa  + r * (HSTR * 2) + sg * 16, Ag + (size_t)r * K + sg * 8);
            cp_async16(sbB + r * (HSTR * 2) + sg * 16, Bg + (size_t)r * K + sg * 8);
        }
        cp_commit();
    };

    // A: m0=[r0-8,k0-8] m1=[r8-16,k0-8] m2=[r0-8,k8-16] m3=[r8-16,k8-16]
    const uint32_t aOff = (uint32_t)(((wm * 64 + (sub & 1) * 8 + lr) * HSTR + (sub >> 1) * 8) * 2);
    // B: m0=[n0-8,k0-8] m1=[n0-8,k8-16] m2=[n8-16,k0-8] m3=[n8-16,k8-16]
    const uint32_t bOff = (uint32_t)(((wn * 32 + (sub >> 1) * 8 + lr) * HSTR + (sub & 1) * 8) * 2);

    float acc[4][4][4] = {};
    int nch = K / 64;

    load_chunk(0, 0);
    for (int c = 0; c < nch; c++) {
        if (c + 1 < nch) { load_chunk(c + 1, (c + 1) & 1); cp_wait<1>(); }
        else             { cp_wait<0>(); }
        __syncthreads();

        uint32_t sA = sb + (c & 1) * HSTG_B;
        uint32_t sB = sA + HT_B;
        #pragma unroll
        for (int ks = 0; ks < 4; ks++) {
            uint32_t af[4][4], bf[4][2];
            #pragma unroll
            for (int mt = 0; mt < 4; mt++)
                ldsm_x4(af[mt][0], af[mt][1], af[mt][2], af[mt][3],
                        sA + aOff + mt * (16 * HSTR * 2) + ks * 32);
            #pragma unroll
            for (int np = 0; np < 2; np++)
                ldsm_x4(bf[2 * np][0], bf[2 * np][1], bf[2 * np + 1][0], bf[2 * np + 1][1],
                        sB + bOff + np * (16 * HSTR * 2) + ks * 32);
            #pragma unroll
            for (int mt = 0; mt < 4; mt++)
                #pragma unroll
                for (int nt = 0; nt < 4; nt++)
                    mma_f16(acc[mt][nt], af[mt], bf[nt]);
        }
        __syncthreads();
    }

    #pragma unroll
    for (int nt = 0; nt < 4; nt++) {
        int n = n0 + wn * 32 + nt * 8 + qd * 2;
        float2 bv = *(const float2*)(bias + n);
        #pragma unroll
        for (int mt = 0; mt < 4; mt++) {
            int m = m0 + wm * 64 + mt * 16 + group;
            float* c4 = acc[mt][nt];
            float2 v0 = make_float2(c4[0] + bv.x, c4[1] + bv.y);
            float2 v1 = make_float2(c4[2] + bv.x, c4[3] + bv.y);
            if (GELU) {
                v0.x *= normcdff(v0.x); v0.y *= normcdff(v0.y);
                v1.x *= normcdff(v1.x); v1.y *= normcdff(v1.y);
            }
            if (RES) {
                float2 r0 = *(const float2*)(res + (size_t)m * N + n);
                float2 r1 = *(const float2*)(res + (size_t)(m + 8) * N + n);
                v0.x += r0.x; v0.y += r0.y; v1.x += r1.x; v1.y += r1.y;
            }
            if (Cf) {
                *(float2*)(Cf + (size_t)m * N + n) = v0;
                *(float2*)(Cf + (size_t)(m + 8) * N + n) = v1;
            }
            if (Ch) {
                *(__half2*)(Ch + (size_t)m * N + n) = __floats2half2_rn(v0.x, v0.y);
                *(__half2*)(Ch + (size_t)(m + 8) * N + n) = __floats2half2_rn(v1.x, v1.y);
            }
        }
    }
}

// ======================= weight convert+transpose: fp32 [K,N] -> fp16 [N,K] ==========
__global__ __launch_bounds__(256) void convert_wT(
    const float* __restrict__ in, __half* __restrict__ out, int K, int N)
{
    __shared__ float tile[64][33];
    int k0 = blockIdx.y * 64, n0 = blockIdx.x * 32;
    int tx = threadIdx.x, ty = threadIdx.y;   // 32 x 8
    #pragma unroll
    for (int i = 0; i < 64; i += 8)
        tile[ty + i][tx] = in[(size_t)(k0 + ty + i) * N + n0 + tx];
    __syncthreads();
    #pragma unroll
    for (int j = 0; j < 4; j++) {
        int n = ty + j * 8;
        __half2 h = __floats2half2_rn(tile[2 * tx][n], tile[2 * tx + 1][n]);
        *(__half2*)(out + (size_t)(n0 + n) * K + k0 + 2 * tx) = h;
    }
}

// ======================= flash attention (fp16 mma, ldmatrix) =======================
#define FS 72
#define FT_B (64 * FS * 2)                 // 9216 B per tile
#define FA_SMEM_B (5 * FT_B)               // Q + 2K + 2V = 46080 B

__global__ __launch_bounds__(128, 2) void flash_h(
    const __half* __restrict__ qkv, __half* __restrict__ O)
{
    extern __shared__ char sm[];
    const uint32_t sb = smem_u32(sm);
    const uint32_t qB = sb;
    const uint32_t kB[2] = { sb + FT_B, sb + 2 * FT_B };
    const uint32_t vB[2] = { sb + 3 * FT_B, sb + 4 * FT_B };

    int qt = blockIdx.x, bh = blockIdx.y;
    int b = bh >> 4, h = bh & 15;
    int q0 = qt * 64;
    int t = threadIdx.x, w = t >> 5, lane = t & 31, gp = lane >> 2, qd = lane & 3;
    int sub = lane >> 3, lr = lane & 7;

    // stage Q
    {
        const __half* qg = qkv + (size_t)(b * T + q0) * (3 * D) + h * HD;
        #pragma unroll
        for (int i = 0; i < 4; i++) {
            int idx = t + i * 128;
            int row = idx >> 3, sg = idx & 7;
            cp_async16(qB + row * (FS * 2) + sg * 16, qg + (size_t)row * (3 * D) + sg * 8);
        }
        cp_commit();
    }

    auto load_kv = [&](int kt, int bf) {
        const __half* kg = qkv + (size_t)(b * T + kt * 64) * (3 * D) + D + h * HD;
        #pragma unroll
        for (int i = 0; i < 4; i++) {
            int idx = t + i * 128;
            int row = idx >> 3, sg = idx & 7;
            const __half* kr = kg + (size_t)row * (3 * D) + sg * 8;
            cp_async16(kB[bf] + row * (FS * 2) + sg * 16, kr);
            cp_async16(vB[bf] + row * (FS * 2) + sg * 16, kr + D);
        }
        cp_commit();
    };

    load_kv(0, 0);
    cp_wait<1>();
    __syncthreads();

    // Q fragments via ldmatrix (A layout)
    const uint32_t aOff = (uint32_t)(((w * 16 + (sub & 1) * 8 + lr) * FS + (sub >> 1) * 8) * 2);
    uint32_t qf[4][4];
    #pragma unroll
    for (int ks = 0; ks < 4; ks++)
        ldsm_x4(qf[ks][0], qf[ks][1], qf[ks][2], qf[ks][3], qB + aOff + ks * 32);

    // K fragment base (B layout)
    const uint32_t kOff = (uint32_t)((((sub >> 1) * 8 + lr) * FS + (sub & 1) * 8) * 2);

    float m0 = -INFINITY, m1 = -INFINITY, l0 = 0.f, l1 = 0.f;
    float o[8][4] = {};

    for (int kt = 0; kt <= qt; kt++) {
        int bf = kt & 1;
        if (kt < qt) { load_kv(kt + 1, bf ^ 1); cp_wait<1>(); }
        else         { cp_wait<0>(); }
        __syncthreads();

        // S = Q @ K^T
        float s[8][4] = {};
        #pragma unroll
        for (int ks = 0; ks < 4; ks++) {
            uint32_t bfr[8][2];
            #pragma unroll
            for (int np = 0; np < 4; np++)
                ldsm_x4(bfr[2 * np][0], bfr[2 * np][1], bfr[2 * np + 1][0], bfr[2 * np + 1][1],
                        kB[bf] + kOff + np * (16 * FS * 2) + ks * 32);
            #pragma unroll
            for (int nt = 0; nt < 8; nt++)
                mma_f16(s[nt], qf[ks], bfr[nt]);
        }
        // scale + causal mask
        bool diag = (kt == qt);
        int r0l = w * 16 + gp;
        #pragma unroll
        for (int nt = 0; nt < 8; nt++) {
            int c = nt * 8 + 2 * qd;
            s[nt][0] *= 0.125f; s[nt][1] *= 0.125f;
            s[nt][2] *= 0.125f; s[nt][3] *= 0.125f;
            if (diag) {
                if (c     > r0l)     s[nt][0] = -INFINITY;
                if (c + 1 > r0l)     s[nt][1] = -INFINITY;
                if (c     > r0l + 8) s[nt][2] = -INFINITY;
                if (c + 1 > r0l + 8) s[nt][3] = -INFINITY;
            }
        }
        // online softmax
        float mx0 = -INFINITY, mx1 = -INFINITY;
        #pragma unroll
        for (int nt = 0; nt < 8; nt++) {
            mx0 = fmaxf(mx0, fmaxf(s[nt][0], s[nt][1]));
            mx1 = fmaxf(mx1, fmaxf(s[nt][2], s[nt][3]));
        }
        mx0 = fmaxf(mx0, __shfl_xor_sync(~0u, mx0, 1));
        mx0 = fmaxf(mx0, __shfl_xor_sync(~0u, mx0, 2));
        mx1 = fmaxf(mx1, __shfl_xor_sync(~0u, mx1, 1));
        mx1 = fmaxf(mx1, __shfl_xor_sync(~0u, mx1, 2));
        float mn0 = fmaxf(m0, mx0), mn1 = fmaxf(m1, mx1);
        float sc0 = __expf(m0 - mn0), sc1 = __expf(m1 - mn1);
        m0 = mn0; m1 = mn1;
        uint32_t pa[8], pb[8];
        float ls0 = 0.f, ls1 = 0.f;
        #pragma unroll
        for (int nt = 0; nt < 8; nt++) {
            float p0 = __expf(s[nt][0] - mn0), p1 = __expf(s[nt][1] - mn0);
            float p2 = __expf(s[nt][2] - mn1), p3 = __expf(s[nt][3] - mn1);
            ls0 += p0 + p1; ls1 += p2 + p3;
            pa[nt] = packh2(p0, p1);
            pb[nt] = packh2(p2, p3);
        }
        ls0 += __shfl_xor_sync(~0u, ls0, 1); ls0 += __shfl_xor_sync(~0u, ls0, 2);
        ls1 += __shfl_xor_sync(~0u, ls1, 1); ls1 += __shfl_xor_sync(~0u, ls1, 2);
        l0 = l0 * sc0 + ls0; l1 = l1 * sc1 + ls1;
        #pragma unroll
        for (int nt = 0; nt < 8; nt++) {
            o[nt][0] *= sc0; o[nt][1] *= sc0; o[nt][2] *= sc1; o[nt][3] *= sc1;
        }
        // O += P @ V
        #pragma unroll
        for (int ks = 0; ks < 4; ks++) {
            uint32_t af[4] = { pa[2 * ks], pb[2 * ks], pa[2 * ks + 1], pb[2 * ks + 1] };
            #pragma unroll
            for (int np = 0; np < 4; np++) {
                int vrow = ks * 16 + (sub & 1) * 8 + lr;
                int vcol = np * 16 + (sub >> 1) * 8;
                uint32_t addr = vB[bf] + (vrow * FS + vcol) * 2;
                uint32_t b0, b1, b2, b3;
                ldsm_x4_trans(b0, b1, b2, b3, addr);
                uint32_t bf0[2] = { b0, b1 }, bf1[2] = { b2, b3 };
                mma_f16(o[2 * np], af, bf0);
                mma_f16(o[2 * np + 1], af, bf1);
            }
        }
        __syncthreads();
    }

    float inv0 = 1.f / l0, inv1 = 1.f / l1;
    int r0 = q0 + w * 16 + gp;
    __half* O0 = O + (size_t)(b * T + r0) * D + h * HD;
    __half* O1 = O0 + (size_t)8 * D;
    #pragma unroll
    for (int nt = 0; nt < 8; nt++) {
        int c = nt * 8 + 2 * qd;
        *(__half2*)(O0 + c) = __floats2half2_rn(o[nt][0] * inv0, o[nt][1] * inv0);
        *(__half2*)(O1 + c) = __floats2half2_rn(o[nt][2] * inv1, o[nt][3] * inv1);
    }
}

// ======================= LayerNorm (fp32 in, fp16 out) =======================
__device__ __forceinline__ float block_sum256(float v, float* red) {
    int t = threadIdx.x;
    #pragma unroll
    for (int o = 16; o > 0; o >>= 1) v += __shfl_xor_sync(0xffffffffu, v, o);
    if ((t & 31) == 0) red[t >> 5] = v;
    __syncthreads();
    if (t < 32) {
        float s = (t < 8) ? red[t] : 0.0f;
        #pragma unroll
        for (int o = 4; o > 0; o >>= 1) s += __shfl_xor_sync(0xffffffffu, s, o);
        if (t == 0) red[0] = s;
    }
    __syncthreads();
    float r = red[0];
    __syncthreads();
    return r;
}

__global__ __launch_bounds__(256) void ln_kernel(
    const float* __restrict__ x, const float* __restrict__ g,
    const float* __restrict__ b, __half* __restrict__ out)
{
    __shared__ float red[32];
    int r = blockIdx.x, t = threadIdx.x;
    const float* xr = x + (size_t)r * D;
    float4 v = *(const float4*)(xr + t * 4);
    float mu = block_sum256(v.x + v.y + v.z + v.w, red) * (1.0f / D);
    float dx = v.x - mu, dy = v.y - mu, dz = v.z - mu, dw = v.w - mu;
    float var = block_sum256(dx * dx + dy * dy + dz * dz + dw * dw, red) * (1.0f / D);
    float inv = rsqrtf(var + 1e-5f);
    float4 gv = *(const float4*)(g + t * 4);
    float4 bv = *(const float4*)(b + t * 4);
    __half2 o01 = __floats2half2_rn(dx * inv * gv.x + bv.x, dy * inv * gv.y + bv.y);
    __half2 o23 = __floats2half2_rn(dz * inv * gv.z + bv.z, dw * inv * gv.w + bv.w);
    uint2 pk = make_uint2(*(uint32_t*)&o01, *(uint32_t*)&o23);
    *(uint2*)(out + (size_t)r * D + t * 4) = pk;
}

// ======================= launch =======================
template<typename Tp>
static Tp* sym_addr(const void* sym) {
    void* p = nullptr;
    cudaGetSymbolAddress(&p, sym);
    return (Tp*)p;
}

extern "C" void kernel_launch(void* const* d_in, const int* in_sizes, int n_in,
                              void* d_out, int out_size)
{
    const float* x     = (const float*)d_in[0];
    const float* w_qkv = (const float*)d_in[1];
    const float* b_qkv = (const float*)d_in[2];
    const float* w_fc  = (const float*)d_in[3];
    const float* b_fc  = (const float*)d_in[4];
    const float* ln1_g = (const float*)d_in[5];
    const float* ln1_b = (const float*)d_in[6];
    const float* ln2_g = (const float*)d_in[7];
    const float* ln2_b = (const float*)d_in[8];
    const float* w1    = (const float*)d_in[9];
    const float* b1    = (const float*)d_in[10];
    const float* w2    = (const float*)d_in[11];
    const float* b2    = (const float*)d_in[12];
    float* out = (float*)d_out;

    __half* p_h16  = sym_addr<__half>(g_h16);
    __half* p_qkv  = sym_addr<__half>(g_qkv16);
    __half* p_attn = sym_addr<__half>(g_attn16);
    float*  p_x1   = sym_addr<float>(g_x1);
    __half* p_h216 = sym_addr<__half>(g_h216);
    __half* p_ffn  = sym_addr<__half>(g_ffn16);
    __half* p_wqkv = sym_addr<__half>(g_wqkv16);
    __half* p_wfc  = sym_addr<__half>(g_wfc16);
    __half* p_w1   = sym_addr<__half>(g_w116);
    __half* p_w2   = sym_addr<__half>(g_w216);

    cudaFuncSetAttribute(gemm_h<false, false>, cudaFuncAttributeMaxDynamicSharedMemorySize, GEMM_SMEM);
    cudaFuncSetAttribute(gemm_h<false, true>,  cudaFuncAttributeMaxDynamicSharedMemorySize, GEMM_SMEM);
    cudaFuncSetAttribute(gemm_h<true,  false>, cudaFuncAttributeMaxDynamicSharedMemorySize, GEMM_SMEM);
    cudaFuncSetAttribute(flash_h, cudaFuncAttributeMaxDynamicSharedMemorySize, FA_SMEM_B);

    // weight convert+transpose: fp32 [K,N] -> fp16 [N,K]
    convert_wT<<<dim3(3 * D / 32, D / 64), dim3(32, 8)>>>(w_qkv, p_wqkv, D, 3 * D);
    convert_wT<<<dim3(D / 32, D / 64),     dim3(32, 8)>>>(w_fc,  p_wfc,  D, D);
    convert_wT<<<dim3(4 * D / 32, D / 64), dim3(32, 8)>>>(w1,    p_w1,   D, 4 * D);
    convert_wT<<<dim3(D / 32, 4 * D / 64), dim3(32, 8)>>>(w2,    p_w2,   4 * D, D);

    // 1. h = LN1(x)  (fp16)
    ln_kernel<<<ROWS, 256>>>(x, ln1_g, ln1_b, p_h16);
    // 2. qkv = h @ w_qkv + b_qkv  (fp16 out)
    gemm_h<false, false><<<dim3(3 * D / 128, ROWS / 128), 256, GEMM_SMEM>>>(
        p_h16, p_wqkv, b_qkv, nullptr, nullptr, p_qkv, ROWS, 3 * D, D);
    // 3. fused attention (fp16 in/out)
    flash_h<<<dim3(T / 64, BHCNT), 128, FA_SMEM_B>>>(p_qkv, p_attn);
    // 4. x1 = x + attn @ w_fc + b_fc  (fp32)
    gemm_h<false, true><<<dim3(D / 128, ROWS / 128), 256, GEMM_SMEM>>>(
        p_attn, p_wfc, b_fc, x, p_x1, nullptr, ROWS, D, D);
    // 5. h2 = LN2(x1)  (fp16)
    ln_kernel<<<ROWS, 256>>>(p_x1, ln2_g, ln2_b, p_h216);
    // 6. ffn = gelu(h2 @ w1 + b1)  (fp16)
    gemm_h<true, false><<<dim3(4 * D / 128, ROWS / 128), 256, GEMM_SMEM>>>(
        p_h216, p_w1, b1, nullptr, nullptr, p_ffn, ROWS, 4 * D, D);
    // 7. out = x1 + ffn @ w2 + b2  (fp32)
    gemm_h<false, true><<<dim3(D / 128, ROWS / 128), 256, GEMM_SMEM>>>(
        p_ffn, p_w2, b2, p_x1, out, nullptr, ROWS, D, 4 * D);
}

// round 15
// speedup vs baseline: 1.2569x; 1.0358x over previous
#include <cuda_runtime.h>
#include <cuda_fp16.h>
#include <math.h>
#include <stdint.h>

// Problem constants
#define BATCH 2
#define T     2048
#define D     1024
#define NH    16
#define HD    64
#define ROWS  (BATCH * T)        // 4096
#define BHCNT (BATCH * NH)       // 32

// ---------------- scratch (device globals; no allocation allowed) -------------
__device__ __half g_h16   [(size_t)ROWS * D];
__device__ __half g_qkv16 [(size_t)ROWS * 3 * D];
__device__ __half g_attn16[(size_t)ROWS * D];
__device__ float  g_x1    [(size_t)ROWS * D];
__device__ __half g_h216  [(size_t)ROWS * D];
__device__ __half g_ffn16 [(size_t)ROWS * 4 * D];
__device__ __half g_wqkv16[(size_t)3 * D * D];   // [N,K] fp16
__device__ __half g_wfc16 [(size_t)D * D];
__device__ __half g_w116  [(size_t)4 * D * D];
__device__ __half g_w216  [(size_t)4 * D * D];

// ======================= common helpers =======================
__device__ __forceinline__ uint32_t smem_u32(const void* p) {
    uint32_t a;
    asm("{ .reg .u64 t; cvta.to.shared.u64 t, %1; cvt.u32.u64 %0, t; }" : "=r"(a) : "l"(p));
    return a;
}
__device__ __forceinline__ void cp_async16(uint32_t s, const void* g) {
    asm volatile("cp.async.ca.shared.global [%0], [%1], 16;" :: "r"(s), "l"(g));
}
__device__ __forceinline__ void cp_commit() {
    asm volatile("cp.async.commit_group;" ::: "memory");
}
template<int N>
__device__ __forceinline__ void cp_wait() {
    asm volatile("cp.async.wait_group %0;" :: "n"(N) : "memory");
}
__device__ __forceinline__ void mma_f16(float* c, const uint32_t* a, const uint32_t* b) {
    asm volatile(
        "mma.sync.aligned.m16n8k16.row.col.f32.f16.f16.f32 "
        "{%0,%1,%2,%3}, {%4,%5,%6,%7}, {%8,%9}, {%0,%1,%2,%3};"
        : "+f"(c[0]), "+f"(c[1]), "+f"(c[2]), "+f"(c[3])
        : "r"(a[0]), "r"(a[1]), "r"(a[2]), "r"(a[3]), "r"(b[0]), "r"(b[1]));
}
__device__ __forceinline__ void ldsm_x4(
    uint32_t& r0, uint32_t& r1, uint32_t& r2, uint32_t& r3, uint32_t addr) {
    asm volatile("ldmatrix.sync.aligned.m8n8.x4.shared.b16 {%0,%1,%2,%3}, [%4];"
        : "=r"(r0), "=r"(r1), "=r"(r2), "=r"(r3) : "r"(addr));
}
__device__ __forceinline__ void ldsm_x4_trans(
    uint32_t& r0, uint32_t& r1, uint32_t& r2, uint32_t& r3, uint32_t addr) {
    asm volatile("ldmatrix.sync.aligned.m8n8.x4.trans.shared.b16 {%0,%1,%2,%3}, [%4];"
        : "=r"(r0), "=r"(r1), "=r"(r2), "=r"(r3) : "r"(addr));
}
__device__ __forceinline__ uint32_t packh2(float a, float b) {
    __half2 h = __floats2half2_rn(a, b);
    return *(uint32_t*)&h;
}

// ======================= fp16 mma GEMM (256 thr, 8 warps, ldmatrix, 2-stage) ==========
#define HSTR 72
#define HT_B (128 * HSTR * 2)
#define HSTG_B (2 * HT_B)
#define GEMM_SMEM (2 * HSTG_B)               // 73728 B -> 2 CTAs/SM (16 warps/SM)

template<bool GELU, bool RES>
__global__ __launch_bounds__(256, 2) void gemm_h(
    const __half* __restrict__ A, const __half* __restrict__ B,
    const float* __restrict__ bias, const float* __restrict__ res,
    float* __restrict__ Cf, __half* __restrict__ Ch, int M, int N, int K)
{
    extern __shared__ char smem[];
    const uint32_t sb = smem_u32(smem);
    int t = threadIdx.x;
    int wid = t >> 5, lane = t & 31;
    int wm = wid >> 2, wn = wid & 3;
    int group = lane >> 2, qd = lane & 3;
    int sub = lane >> 3, lr = lane & 7;
    int m0 = blockIdx.y * 128, n0 = blockIdx.x * 128;

    auto load_chunk = [&](int c, int buf) {
        uint32_t sa = sb + buf * HSTG_B;
        uint32_t sbB = sa + HT_B;
        const __half* Ag = A + (size_t)m0 * K + c * 64;
        const __half* Bg = B + (size_t)n0 * K + c * 64;
        #pragma unroll
        for (int j = 0; j < 4; j++) {
            int idx = t + j * 256;
            int r = idx >> 3, sg = idx & 7;
            cp_async16(sa  + r * (HSTR * 2) + sg * 16, Ag + (size_t)r * K + sg * 8);
            cp_async16(sbB + r * (HSTR * 2) + sg * 16, Bg + (size_t)r * K + sg * 8);
        }
        cp_commit();
    };

    const uint32_t aOff = (uint32_t)(((wm * 64 + (sub & 1) * 8 + lr) * HSTR + (sub >> 1) * 8) * 2);
    const uint32_t bOff = (uint32_t)(((wn * 32 + (sub >> 1) * 8 + lr) * HSTR + (sub & 1) * 8) * 2);

    float acc[4][4][4] = {};
    int nch = K / 64;

    load_chunk(0, 0);
    for (int c = 0; c < nch; c++) {
        if (c + 1 < nch) { load_chunk(c + 1, (c + 1) & 1); cp_wait<1>(); }
        else             { cp_wait<0>(); }
        __syncthreads();

        uint32_t sA = sb + (c & 1) * HSTG_B;
        uint32_t sB = sA + HT_B;
        #pragma unroll
        for (int ks = 0; ks < 4; ks++) {
            uint32_t af[4][4], bf[4][2];
            #pragma unroll
            for (int mt = 0; mt < 4; mt++)
                ldsm_x4(af[mt][0], af[mt][1], af[mt][2], af[mt][3],
                        sA + aOff + mt * (16 * HSTR * 2) + ks * 32);
            #pragma unroll
            for (int np = 0; np < 2; np++)
                ldsm_x4(bf[2 * np][0], bf[2 * np][1], bf[2 * np + 1][0], bf[2 * np + 1][1],
                        sB + bOff + np * (16 * HSTR * 2) + ks * 32);
            #pragma unroll
            for (int mt = 0; mt < 4; mt++)
                #pragma unroll
                for (int nt = 0; nt < 4; nt++)
                    mma_f16(acc[mt][nt], af[mt], bf[nt]);
        }
        __syncthreads();
    }

    #pragma unroll
    for (int nt = 0; nt < 4; nt++) {
        int n = n0 + wn * 32 + nt * 8 + qd * 2;
        float2 bv = *(const float2*)(bias + n);
        #pragma unroll
        for (int mt = 0; mt < 4; mt++) {
            int m = m0 + wm * 64 + mt * 16 + group;
            float* c4 = acc[mt][nt];
            float2 v0 = make_float2(c4[0] + bv.x, c4[1] + bv.y);
            float2 v1 = make_float2(c4[2] + bv.x, c4[3] + bv.y);
            if (GELU) {
                v0.x *= normcdff(v0.x); v0.y *= normcdff(v0.y);
                v1.x *= normcdff(v1.x); v1.y *= normcdff(v1.y);
            }
            if (RES) {
                float2 r0 = *(const float2*)(res + (size_t)m * N + n);
                float2 r1 = *(const float2*)(res + (size_t)(m + 8) * N + n);
                v0.x += r0.x; v0.y += r0.y; v1.x += r1.x; v1.y += r1.y;
            }
            if (Cf) {
                *(float2*)(Cf + (size_t)m * N + n) = v0;
                *(float2*)(Cf + (size_t)(m + 8) * N + n) = v1;
            }
            if (Ch) {
                *(__half2*)(Ch + (size_t)m * N + n) = __floats2half2_rn(v0.x, v0.y);
                *(__half2*)(Ch + (size_t)(m + 8) * N + n) = __floats2half2_rn(v1.x, v1.y);
            }
        }
    }
}

// ======================= fused weight convert+transpose (all 4 weights) =============
// Tile = 64 k x 32 n. Compile-time cumulative tile ranges (no constant-mem copy!).
#define TW0 ((D / 64) * (3 * D / 32))            // 1536
#define TW1 ((D / 64) * (D / 32))                // 512
#define TW2 ((D / 64) * (4 * D / 32))            // 2048
#define TW3 ((4 * D / 64) * (D / 32))            // 2048
#define CVT_TILES (TW0 + TW1 + TW2 + TW3)

__global__ __launch_bounds__(256) void convert_all(
    const float* __restrict__ in0, __half* __restrict__ out0,
    const float* __restrict__ in1, __half* __restrict__ out1,
    const float* __restrict__ in2, __half* __restrict__ out2,
    const float* __restrict__ in3, __half* __restrict__ out3)
{
    __shared__ float tile[64][33];
    int bid = blockIdx.x;
    const float* in; __half* out; int K, N, local;
    if (bid < TW0)                   { in = in0; out = out0; K = D;     N = 3 * D; local = bid; }
    else if (bid < TW0 + TW1)        { in = in1; out = out1; K = D;     N = D;     local = bid - TW0; }
    else if (bid < TW0 + TW1 + TW2)  { in = in2; out = out2; K = D;     N = 4 * D; local = bid - TW0 - TW1; }
    else                             { in = in3; out = out3; K = 4 * D; N = D;     local = bid - TW0 - TW1 - TW2; }
    int tiles_n = N / 32;
    int k0 = (local / tiles_n) * 64, n0 = (local % tiles_n) * 32;
    int tx = threadIdx.x & 31, ty = threadIdx.x >> 5;   // 32 x 8
    #pragma unroll
    for (int i = 0; i < 64; i += 8)
        tile[ty + i][tx] = in[(size_t)(k0 + ty + i) * N + n0 + tx];
    __syncthreads();
    #pragma unroll
    for (int j = 0; j < 4; j++) {
        int n = ty + j * 8;
        __half2 h = __floats2half2_rn(tile[2 * tx][n], tile[2 * tx + 1][n]);
        *(__half2*)(out + (size_t)(n0 + n) * K + k0 + 2 * tx) = h;
    }
}

// ======================= flash attention (fp16 mma, paired q-tiles, occ 4) ==========
#define FS 72
#define FT_B (64 * FS * 2)                 // 9216 B per tile
#define FA_SMEM_B (5 * FT_B)               // Q + 2K + 2V = 46080 B

__global__ __launch_bounds__(128, 4) void flash_h(
    const __half* __restrict__ qkv, __half* __restrict__ O)
{
    extern __shared__ char sm[];
    const uint32_t sb = smem_u32(sm);
    const uint32_t qB = sb;
    const uint32_t kB[2] = { sb + FT_B, sb + 2 * FT_B };
    const uint32_t vB[2] = { sb + 3 * FT_B, sb + 4 * FT_B };

    int bh = blockIdx.y;
    int b = bh >> 4, h = bh & 15;
    int t = threadIdx.x, w = t >> 5, lane = t & 31, gp = lane >> 2, qd = lane & 3;
    int sub = lane >> 3, lr = lane & 7;

    const uint32_t aOff = (uint32_t)(((w * 16 + (sub & 1) * 8 + lr) * FS + (sub >> 1) * 8) * 2);
    const uint32_t kOff = (uint32_t)((((sub >> 1) * 8 + lr) * FS + (sub & 1) * 8) * 2);

    auto load_kv = [&](int kt, int bf) {
        const __half* kg = qkv + (size_t)(b * T + kt * 64) * (3 * D) + D + h * HD;
        #pragma unroll
        for (int i = 0; i < 4; i++) {
            int idx = t + i * 128;
            int row = idx >> 3, sg = idx & 7;
            const __half* kr = kg + (size_t)row * (3 * D) + sg * 8;
            cp_async16(kB[bf] + row * (FS * 2) + sg * 16, kr);
            cp_async16(vB[bf] + row * (FS * 2) + sg * 16, kr + D);
        }
        cp_commit();
    };

    // paired q-tiles: (i, 31-i) -> uniform 33 k-tiles per CTA
    int qts[2] = { (int)blockIdx.x, 31 - (int)blockIdx.x };

    for (int ph = 0; ph < 2; ph++) {
        int qt = qts[ph];
        int q0 = qt * 64;

        // stage Q
        {
            const __half* qg = qkv + (size_t)(b * T + q0) * (3 * D) + h * HD;
            #pragma unroll
            for (int i = 0; i < 4; i++) {
                int idx = t + i * 128;
                int row = idx >> 3, sg = idx & 7;
                cp_async16(qB + row * (FS * 2) + sg * 16, qg + (size_t)row * (3 * D) + sg * 8);
            }
            cp_commit();
        }
        load_kv(0, 0);
        cp_wait<1>();
        __syncthreads();

        uint32_t qf[4][4];
        #pragma unroll
        for (int ks = 0; ks < 4; ks++)
            ldsm_x4(qf[ks][0], qf[ks][1], qf[ks][2], qf[ks][3], qB + aOff + ks * 32);

        float m0 = -INFINITY, m1 = -INFINITY, l0 = 0.f, l1 = 0.f;
        float o[8][4] = {};

        for (int kt = 0; kt <= qt; kt++) {
            int bf = kt & 1;
            if (kt < qt) { load_kv(kt + 1, bf ^ 1); cp_wait<1>(); }
            else         { cp_wait<0>(); }
            __syncthreads();

            // S = Q @ K^T
            float s[8][4] = {};
            #pragma unroll
            for (int ks = 0; ks < 4; ks++) {
                uint32_t bfr[8][2];
                #pragma unroll
                for (int np = 0; np < 4; np++)
                    ldsm_x4(bfr[2 * np][0], bfr[2 * np][1], bfr[2 * np + 1][0], bfr[2 * np + 1][1],
                            kB[bf] + kOff + np * (16 * FS * 2) + ks * 32);
                #pragma unroll
                for (int nt = 0; nt < 8; nt++)
                    mma_f16(s[nt], qf[ks], bfr[nt]);
            }
            bool diag = (kt == qt);
            int r0l = w * 16 + gp;
            #pragma unroll
            for (int nt = 0; nt < 8; nt++) {
                int c = nt * 8 + 2 * qd;
                s[nt][0] *= 0.125f; s[nt][1] *= 0.125f;
                s[nt][2] *= 0.125f; s[nt][3] *= 0.125f;
                if (diag) {
                    if (c     > r0l)     s[nt][0] = -INFINITY;
                    if (c + 1 > r0l)     s[nt][1] = -INFINITY;
                    if (c     > r0l + 8) s[nt][2] = -INFINITY;
                    if (c + 1 > r0l + 8) s[nt][3] = -INFINITY;
                }
            }
            float mx0 = -INFINITY, mx1 = -INFINITY;
            #pragma unroll
            for (int nt = 0; nt < 8; nt++) {
                mx0 = fmaxf(mx0, fmaxf(s[nt][0], s[nt][1]));
                mx1 = fmaxf(mx1, fmaxf(s[nt][2], s[nt][3]));
            }
            mx0 = fmaxf(mx0, __shfl_xor_sync(~0u, mx0, 1));
            mx0 = fmaxf(mx0, __shfl_xor_sync(~0u, mx0, 2));
            mx1 = fmaxf(mx1, __shfl_xor_sync(~0u, mx1, 1));
            mx1 = fmaxf(mx1, __shfl_xor_sync(~0u, mx1, 2));
            float mn0 = fmaxf(m0, mx0), mn1 = fmaxf(m1, mx1);
            float sc0 = __expf(m0 - mn0), sc1 = __expf(m1 - mn1);
            m0 = mn0; m1 = mn1;
            uint32_t pa[8], pb[8];
            float ls0 = 0.f, ls1 = 0.f;
            #pragma unroll
            for (int nt = 0; nt < 8; nt++) {
                float p0 = __expf(s[nt][0] - mn0), p1 = __expf(s[nt][1] - mn0);
                float p2 = __expf(s[nt][2] - mn1), p3 = __expf(s[nt][3] - mn1);
                ls0 += p0 + p1; ls1 += p2 + p3;
                pa[nt] = packh2(p0, p1);
                pb[nt] = packh2(p2, p3);
            }
            ls0 += __shfl_xor_sync(~0u, ls0, 1); ls0 += __shfl_xor_sync(~0u, ls0, 2);
            ls1 += __shfl_xor_sync(~0u, ls1, 1); ls1 += __shfl_xor_sync(~0u, ls1, 2);
            l0 = l0 * sc0 + ls0; l1 = l1 * sc1 + ls1;
            #pragma unroll
            for (int nt = 0; nt < 8; nt++) {
                o[nt][0] *= sc0; o[nt][1] *= sc0; o[nt][2] *= sc1; o[nt][3] *= sc1;
            }
            // O += P @ V
            #pragma unroll
            for (int ks = 0; ks < 4; ks++) {
                uint32_t af[4] = { pa[2 * ks], pb[2 * ks], pa[2 * ks + 1], pb[2 * ks + 1] };
                #pragma unroll
                for (int np = 0; np < 4; np++) {
                    int vrow = ks * 16 + (sub & 1) * 8 + lr;
                    int vcol = np * 16 + (sub >> 1) * 8;
                    uint32_t addr = vB[bf] + (vrow * FS + vcol) * 2;
                    uint32_t b0, b1, b2, b3;
                    ldsm_x4_trans(b0, b1, b2, b3, addr);
                    uint32_t bf0[2] = { b0, b1 }, bf1[2] = { b2, b3 };
                    mma_f16(o[2 * np], af, bf0);
                    mma_f16(o[2 * np + 1], af, bf1);
                }
            }
            __syncthreads();
        }

        float inv0 = 1.f / l0, inv1 = 1.f / l1;
        int r0 = q0 + w * 16 + gp;
        __half* O0 = O + (size_t)(b * T + r0) * D + h * HD;
        __half* O1 = O0 + (size_t)8 * D;
        #pragma unroll
        for (int nt = 0; nt < 8; nt++) {
            int c = nt * 8 + 2 * qd;
            *(__half2*)(O0 + c) = __floats2half2_rn(o[nt][0] * inv0, o[nt][1] * inv0);
            *(__half2*)(O1 + c) = __floats2half2_rn(o[nt][2] * inv1, o[nt][3] * inv1);
        }
    }
}

// ======================= LayerNorm (fp32 in, fp16 out) =======================
__device__ __forceinline__ float block_sum256(float v, float* red) {
    int t = threadIdx.x;
    #pragma unroll
    for (int o = 16; o > 0; o >>= 1) v += __shfl_xor_sync(0xffffffffu, v, o);
    if ((t & 31) == 0) red[t >> 5] = v;
    __syncthreads();
    if (t < 32) {
        float s = (t < 8) ? red[t] : 0.0f;
        #pragma unroll
        for (int o = 4; o > 0; o >>= 1) s += __shfl_xor_sync(0xffffffffu, s, o);
        if (t == 0) red[0] = s;
    }
    __syncthreads();
    float r = red[0];
    __syncthreads();
    return r;
}

__global__ __launch_bounds__(256) void ln_kernel(
    const float* __restrict__ x, const float* __restrict__ g,
    const float* __restrict__ b, __half* __restrict__ out)
{
    __shared__ float red[32];
    int r = blockIdx.x, t = threadIdx.x;
    const float* xr = x + (size_t)r * D;
    float4 v = *(const float4*)(xr + t * 4);
    float mu = block_sum256(v.x + v.y + v.z + v.w, red) * (1.0f / D);
    float dx = v.x - mu, dy = v.y - mu, dz = v.z - mu, dw = v.w - mu;
    float var = block_sum256(dx * dx + dy * dy + dz * dz + dw * dw, red) * (1.0f / D);
    float inv = rsqrtf(var + 1e-5f);
    float4 gv = *(const float4*)(g + t * 4);
    float4 bv = *(const float4*)(b + t * 4);
    __half2 o01 = __floats2half2_rn(dx * inv * gv.x + bv.x, dy * inv * gv.y + bv.y);
    __half2 o23 = __floats2half2_rn(dz * inv * gv.z + bv.z, dw * inv * gv.w + bv.w);
    uint2 pk = make_uint2(*(uint32_t*)&o01, *(uint32_t*)&o23);
    *(uint2*)(out + (size_t)r * D + t * 4) = pk;
}

// ======================= launch =======================
template<typename Tp>
static Tp* sym_addr(const void* sym) {
    void* p = nullptr;
    cudaGetSymbolAddress(&p, sym);
    return (Tp*)p;
}

extern "C" void kernel_launch(void* const* d_in, const int* in_sizes, int n_in,
                              void* d_out, int out_size)
{
    const float* x     = (const float*)d_in[0];
    const float* w_qkv = (const float*)d_in[1];
    const float* b_qkv = (const float*)d_in[2];
    const float* w_fc  = (const float*)d_in[3];
    const float* b_fc  = (const float*)d_in[4];
    const float* ln1_g = (const float*)d_in[5];
    const float* ln1_b = (const float*)d_in[6];
    const float* ln2_g = (const float*)d_in[7];
    const float* ln2_b = (const float*)d_in[8];
    const float* w1    = (const float*)d_in[9];
    const float* b1    = (const float*)d_in[10];
    const float* w2    = (const float*)d_in[11];
    const float* b2    = (const float*)d_in[12];
    float* out = (float*)d_out;

    __half* p_h16  = sym_addr<__half>(g_h16);
    __half* p_qkv  = sym_addr<__half>(g_qkv16);
    __half* p_attn = sym_addr<__half>(g_attn16);
    float*  p_x1   = sym_addr<float>(g_x1);
    __half* p_h216 = sym_addr<__half>(g_h216);
    __half* p_ffn  = sym_addr<__half>(g_ffn16);
    __half* p_wqkv = sym_addr<__half>(g_wqkv16);
    __half* p_wfc  = sym_addr<__half>(g_wfc16);
    __half* p_w1   = sym_addr<__half>(g_w116);
    __half* p_w2   = sym_addr<__half>(g_w216);

    cudaFuncSetAttribute(gemm_h<false, false>, cudaFuncAttributeMaxDynamicSharedMemorySize, GEMM_SMEM);
    cudaFuncSetAttribute(gemm_h<false, true>,  cudaFuncAttributeMaxDynamicSharedMemorySize, GEMM_SMEM);
    cudaFuncSetAttribute(gemm_h<true,  false>, cudaFuncAttributeMaxDynamicSharedMemorySize, GEMM_SMEM);
    cudaFuncSetAttribute(flash_h, cudaFuncAttributeMaxDynamicSharedMemorySize, FA_SMEM_B);

    // fused weight converts (ranges are compile-time)
    convert_all<<<CVT_TILES, 256>>>(
        w_qkv, p_wqkv, w_fc, p_wfc, w1, p_w1, w2, p_w2);

    // 1. h = LN1(x)  (fp16)
    ln_kernel<<<ROWS, 256>>>(x, ln1_g, ln1_b, p_h16);
    // 2. qkv = h @ w_qkv + b_qkv  (fp16 out)
    gemm_h<false, false><<<dim3(3 * D / 128, ROWS / 128), 256, GEMM_SMEM>>>(
        p_h16, p_wqkv, b_qkv, nullptr, nullptr, p_qkv, ROWS, 3 * D, D);
    // 3. fused attention (fp16 in/out, paired q-tiles, occ 4)
    flash_h<<<dim3(T / 128, BHCNT), 128, FA_SMEM_B>>>(p_qkv, p_attn);
    // 4. x1 = x + attn @ w_fc + b_fc  (fp32)
    gemm_h<false, true><<<dim3(D / 128, ROWS / 128), 256, GEMM_SMEM>>>(
        p_attn, p_wfc, b_fc, x, p_x1, nullptr, ROWS, D, D);
    // 5. h2 = LN2(x1)  (fp16)
    ln_kernel<<<ROWS, 256>>>(p_x1, ln2_g, ln2_b, p_h216);
    // 6. ffn = gelu(h2 @ w1 + b1)  (fp16)
    gemm_h<true, false><<<dim3(4 * D / 128, ROWS / 128), 256, GEMM_SMEM>>>(
        p_h216, p_w1, b1, nullptr, nullptr, p_ffn, ROWS, 4 * D, D);
    // 7. out = x1 + ffn @ w2 + b2  (fp32)
    gemm_h<false, true><<<dim3(D / 128, ROWS / 128), 256, GEMM_SMEM>>>(
        p_ffn, p_w2, b2, p_x1, out, nullptr, ROWS, D, 4 * D);
}

// round 16
// speedup vs baseline: 1.2578x; 1.0008x over previous
#include <cuda_runtime.h>
#include <cuda_fp16.h>
#include <math.h>
#include <stdint.h>

// Problem constants
#define BATCH 2
#define T     2048
#define D     1024
#define NH    16
#define HD    64
#define ROWS  (BATCH * T)        // 4096
#define BHCNT (BATCH * NH)       // 32

// ---------------- scratch (device globals; no allocation allowed) -------------
__device__ __half g_h16   [(size_t)ROWS * D];
__device__ __half g_qkv16 [(size_t)ROWS * 3 * D];
__device__ __half g_attn16[(size_t)ROWS * D];
__device__ float  g_x1    [(size_t)ROWS * D];
__device__ __half g_h216  [(size_t)ROWS * D];
__device__ __half g_ffn16 [(size_t)ROWS * 4 * D];
__device__ __half g_wqkv16[(size_t)3 * D * D];   // [N,K] fp16
__device__ __half g_wfc16 [(size_t)D * D];
__device__ __half g_w116  [(size_t)4 * D * D];
__device__ __half g_w216  [(size_t)4 * D * D];

// ======================= common helpers =======================
__device__ __forceinline__ uint32_t smem_u32(const void* p) {
    uint32_t a;
    asm("{ .reg .u64 t; cvta.to.shared.u64 t, %1; cvt.u32.u64 %0, t; }" : "=r"(a) : "l"(p));
    return a;
}
__device__ __forceinline__ void cp_async16(uint32_t s, const void* g) {
    asm volatile("cp.async.ca.shared.global [%0], [%1], 16;" :: "r"(s), "l"(g));
}
__device__ __forceinline__ void cp_commit() {
    asm volatile("cp.async.commit_group;" ::: "memory");
}
template<int N>
__device__ __forceinline__ void cp_wait() {
    asm volatile("cp.async.wait_group %0;" :: "n"(N) : "memory");
}
__device__ __forceinline__ void mma_f16(float* c, const uint32_t* a, const uint32_t* b) {
    asm volatile(
        "mma.sync.aligned.m16n8k16.row.col.f32.f16.f16.f32 "
        "{%0,%1,%2,%3}, {%4,%5,%6,%7}, {%8,%9}, {%0,%1,%2,%3};"
        : "+f"(c[0]), "+f"(c[1]), "+f"(c[2]), "+f"(c[3])
        : "r"(a[0]), "r"(a[1]), "r"(a[2]), "r"(a[3]), "r"(b[0]), "r"(b[1]));
}
__device__ __forceinline__ void ldsm_x4(
    uint32_t& r0, uint32_t& r1, uint32_t& r2, uint32_t& r3, uint32_t addr) {
    asm volatile("ldmatrix.sync.aligned.m8n8.x4.shared.b16 {%0,%1,%2,%3}, [%4];"
        : "=r"(r0), "=r"(r1), "=r"(r2), "=r"(r3) : "r"(addr));
}
__device__ __forceinline__ void ldsm_x4_trans(
    uint32_t& r0, uint32_t& r1, uint32_t& r2, uint32_t& r3, uint32_t addr) {
    asm volatile("ldmatrix.sync.aligned.m8n8.x4.trans.shared.b16 {%0,%1,%2,%3}, [%4];"
        : "=r"(r0), "=r"(r1), "=r"(r2), "=r"(r3) : "r"(addr));
}
__device__ __forceinline__ uint32_t packh2(float a, float b) {
    __half2 h = __floats2half2_rn(a, b);
    return *(uint32_t*)&h;
}

// ======================= fp16 mma GEMM (256 thr, 8 warps, ldmatrix, 2-stage) ==========
#define HSTR 72
#define HT_B (128 * HSTR * 2)
#define HSTG_B (2 * HT_B)
#define GEMM_SMEM (2 * HSTG_B)               // 73728 B -> 2 CTAs/SM (16 warps/SM)

template<bool GELU, bool RES>
__global__ __launch_bounds__(256, 2) void gemm_h(
    const __half* __restrict__ A, const __half* __restrict__ B,
    const float* __restrict__ bias, const float* __restrict__ res,
    float* __restrict__ Cf, __half* __restrict__ Ch, int M, int N, int K)
{
    extern __shared__ char smem[];
    const uint32_t sb = smem_u32(smem);
    int t = threadIdx.x;
    int wid = t >> 5, lane = t & 31;
    int wm = wid >> 2, wn = wid & 3;
    int group = lane >> 2, qd = lane & 3;
    int sub = lane >> 3, lr = lane & 7;
    int m0 = blockIdx.y * 128, n0 = blockIdx.x * 128;

    auto load_chunk = [&](int c, int buf) {
        uint32_t sa = sb + buf * HSTG_B;
        uint32_t sbB = sa + HT_B;
        const __half* Ag = A + (size_t)m0 * K + c * 64;
        const __half* Bg = B + (size_t)n0 * K + c * 64;
        #pragma unroll
        for (int j = 0; j < 4; j++) {
            int idx = t + j * 256;
            int r = idx >> 3, sg = idx & 7;
            cp_async16(sa  + r * (HSTR * 2) + sg * 16, Ag + (size_t)r * K + sg * 8);
            cp_async16(sbB + r * (HSTR * 2) + sg * 16, Bg + (size_t)r * K + sg * 8);
        }
        cp_commit();
    };

    const uint32_t aOff = (uint32_t)(((wm * 64 + (sub & 1) * 8 + lr) * HSTR + (sub >> 1) * 8) * 2);
    const uint32_t bOff = (uint32_t)(((wn * 32 + (sub >> 1) * 8 + lr) * HSTR + (sub & 1) * 8) * 2);

    float acc[4][4][4] = {};
    int nch = K / 64;

    load_chunk(0, 0);
    for (int c = 0; c < nch; c++) {
        if (c + 1 < nch) { load_chunk(c + 1, (c + 1) & 1); cp_wait<1>(); }
        else             { cp_wait<0>(); }
        __syncthreads();

        uint32_t sA = sb + (c & 1) * HSTG_B;
        uint32_t sB = sA + HT_B;
        #pragma unroll
        for (int ks = 0; ks < 4; ks++) {
            uint32_t af[4][4], bf[4][2];
            #pragma unroll
            for (int mt = 0; mt < 4; mt++)
                ldsm_x4(af[mt][0], af[mt][1], af[mt][2], af[mt][3],
                        sA + aOff + mt * (16 * HSTR * 2) + ks * 32);
            #pragma unroll
            for (int np = 0; np < 2; np++)
                ldsm_x4(bf[2 * np][0], bf[2 * np][1], bf[2 * np + 1][0], bf[2 * np + 1][1],
                        sB + bOff + np * (16 * HSTR * 2) + ks * 32);
            #pragma unroll
            for (int mt = 0; mt < 4; mt++)
                #pragma unroll
                for (int nt = 0; nt < 4; nt++)
                    mma_f16(acc[mt][nt], af[mt], bf[nt]);
        }
        __syncthreads();
    }

    #pragma unroll
    for (int nt = 0; nt < 4; nt++) {
        int n = n0 + wn * 32 + nt * 8 + qd * 2;
        float2 bv = *(const float2*)(bias + n);
        #pragma unroll
        for (int mt = 0; mt < 4; mt++) {
            int m = m0 + wm * 64 + mt * 16 + group;
            float* c4 = acc[mt][nt];
            float2 v0 = make_float2(c4[0] + bv.x, c4[1] + bv.y);
            float2 v1 = make_float2(c4[2] + bv.x, c4[3] + bv.y);
            if (GELU) {
                v0.x *= normcdff(v0.x); v0.y *= normcdff(v0.y);
                v1.x *= normcdff(v1.x); v1.y *= normcdff(v1.y);
            }
            if (RES) {
                float2 r0 = *(const float2*)(res + (size_t)m * N + n);
                float2 r1 = *(const float2*)(res + (size_t)(m + 8) * N + n);
                v0.x += r0.x; v0.y += r0.y; v1.x += r1.x; v1.y += r1.y;
            }
            if (Cf) {
                *(float2*)(Cf + (size_t)m * N + n) = v0;
                *(float2*)(Cf + (size_t)(m + 8) * N + n) = v1;
            }
            if (Ch) {
                *(__half2*)(Ch + (size_t)m * N + n) = __floats2half2_rn(v0.x, v0.y);
                *(__half2*)(Ch + (size_t)(m + 8) * N + n) = __floats2half2_rn(v1.x, v1.y);
            }
        }
    }
}

// ======================= fused weight convert+transpose (all 4 weights) =============
#define TW0 ((D / 64) * (3 * D / 32))
#define TW1 ((D / 64) * (D / 32))
#define TW2 ((D / 64) * (4 * D / 32))
#define TW3 ((4 * D / 64) * (D / 32))
#define CVT_TILES (TW0 + TW1 + TW2 + TW3)

__global__ __launch_bounds__(256) void convert_all(
    const float* __restrict__ in0, __half* __restrict__ out0,
    const float* __restrict__ in1, __half* __restrict__ out1,
    const float* __restrict__ in2, __half* __restrict__ out2,
    const float* __restrict__ in3, __half* __restrict__ out3)
{
    __shared__ float tile[64][33];
    int bid = blockIdx.x;
    const float* in; __half* out; int K, N, local;
    if (bid < TW0)                   { in = in0; out = out0; K = D;     N = 3 * D; local = bid; }
    else if (bid < TW0 + TW1)        { in = in1; out = out1; K = D;     N = D;     local = bid - TW0; }
    else if (bid < TW0 + TW1 + TW2)  { in = in2; out = out2; K = D;     N = 4 * D; local = bid - TW0 - TW1; }
    else                             { in = in3; out = out3; K = 4 * D; N = D;     local = bid - TW0 - TW1 - TW2; }
    int tiles_n = N / 32;
    int k0 = (local / tiles_n) * 64, n0 = (local % tiles_n) * 32;
    int tx = threadIdx.x & 31, ty = threadIdx.x >> 5;
    #pragma unroll
    for (int i = 0; i < 64; i += 8)
        tile[ty + i][tx] = in[(size_t)(k0 + ty + i) * N + n0 + tx];
    __syncthreads();
    #pragma unroll
    for (int j = 0; j < 4; j++) {
        int n = ty + j * 8;
        __half2 h = __floats2half2_rn(tile[2 * tx][n], tile[2 * tx + 1][n]);
        *(__half2*)(out + (size_t)(n0 + n) * K + k0 + 2 * tx) = h;
    }
}

// ======================= flash attention (256 thr, q-tile 128, paired) ==========
#define FS 72
#define FQ_B (128 * FS * 2)                // Q tile 18432 B
#define FKV_B (64 * FS * 2)                // K/V tile 9216 B
#define FA_SMEM_B (FQ_B + 4 * FKV_B)       // 55296 B

__global__ __launch_bounds__(256, 2) void flash_h(
    const __half* __restrict__ qkv, __half* __restrict__ O)
{
    extern __shared__ char sm[];
    const uint32_t sb = smem_u32(sm);
    const uint32_t qB = sb;
    const uint32_t kB[2] = { sb + FQ_B, sb + FQ_B + FKV_B };
    const uint32_t vB[2] = { sb + FQ_B + 2 * FKV_B, sb + FQ_B + 3 * FKV_B };

    int bh = blockIdx.y;
    int b = bh >> 4, h = bh & 15;
    int t = threadIdx.x, w = t >> 5, lane = t & 31, gp = lane >> 2, qd = lane & 3;
    int sub = lane >> 3, lr = lane & 7;

    const uint32_t aOff = (uint32_t)(((w * 16 + (sub & 1) * 8 + lr) * FS + (sub >> 1) * 8) * 2);
    const uint32_t kOff = (uint32_t)((((sub >> 1) * 8 + lr) * FS + (sub & 1) * 8) * 2);

    auto load_kv = [&](int kt, int bf) {
        const __half* kg = qkv + (size_t)(b * T + kt * 64) * (3 * D) + D + h * HD;
        #pragma unroll
        for (int i = 0; i < 2; i++) {
            int idx = t + i * 256;
            int row = idx >> 3, sg = idx & 7;
            const __half* kr = kg + (size_t)row * (3 * D) + sg * 8;
            cp_async16(kB[bf] + row * (FS * 2) + sg * 16, kr);
            cp_async16(vB[bf] + row * (FS * 2) + sg * 16, kr + D);
        }
        cp_commit();
    };

    // paired q-tiles of 128 rows: (i, 15-i) -> uniform 34 k-tiles per CTA
    int qts[2] = { (int)blockIdx.x, 15 - (int)blockIdx.x };

    for (int ph = 0; ph < 2; ph++) {
        int qt = qts[ph];
        int q0 = qt * 128;
        int nkt = 2 * qt + 2;                // number of 64-wide k-tiles

        // stage Q (128 rows x 8 segs = 1024 segs)
        {
            const __half* qg = qkv + (size_t)(b * T + q0) * (3 * D) + h * HD;
            #pragma unroll
            for (int i = 0; i < 4; i++) {
                int idx = t + i * 256;
                int row = idx >> 3, sg = idx & 7;
                cp_async16(qB + row * (FS * 2) + sg * 16, qg + (size_t)row * (3 * D) + sg * 8);
            }
            cp_commit();
        }
        load_kv(0, 0);
        cp_wait<1>();
        __syncthreads();

        uint32_t qf[4][4];
        #pragma unroll
        for (int ks = 0; ks < 4; ks++)
            ldsm_x4(qf[ks][0], qf[ks][1], qf[ks][2], qf[ks][3], qB + aOff + ks * 32);

        float m0 = -INFINITY, m1 = -INFINITY, l0 = 0.f, l1 = 0.f;
        float o[8][4] = {};
        int qrow = q0 + w * 16 + gp;         // rows qrow, qrow+8 for this thread

        for (int kt = 0; kt < nkt; kt++) {
            int bf = kt & 1;
            if (kt + 1 < nkt) { load_kv(kt + 1, bf ^ 1); cp_wait<1>(); }
            else              { cp_wait<0>(); }
            __syncthreads();

            // S = Q @ K^T
            float s[8][4] = {};
            #pragma unroll
            for (int ks = 0; ks < 4; ks++) {
                uint32_t bfr[8][2];
                #pragma unroll
                for (int np = 0; np < 4; np++)
                    ldsm_x4(bfr[2 * np][0], bfr[2 * np][1], bfr[2 * np + 1][0], bfr[2 * np + 1][1],
                            kB[bf] + kOff + np * (16 * FS * 2) + ks * 32);
                #pragma unroll
                for (int nt = 0; nt < 8; nt++)
                    mma_f16(s[nt], qf[ks], bfr[nt]);
            }
            // scale + causal mask (global compare; only near-diagonal tiles mask)
            int kbase = kt * 64;
            bool need_mask = (kbase + 63) > qrow;
            #pragma unroll
            for (int nt = 0; nt < 8; nt++) {
                int c = kbase + nt * 8 + 2 * qd;
                s[nt][0] *= 0.125f; s[nt][1] *= 0.125f;
                s[nt][2] *= 0.125f; s[nt][3] *= 0.125f;
                if (need_mask) {
                    if (c     > qrow)     s[nt][0] = -INFINITY;
                    if (c + 1 > qrow)     s[nt][1] = -INFINITY;
                    if (c     > qrow + 8) s[nt][2] = -INFINITY;
                    if (c + 1 > qrow + 8) s[nt][3] = -INFINITY;
                }
            }
            // online softmax
            float mx0 = -INFINITY, mx1 = -INFINITY;
            #pragma unroll
            for (int nt = 0; nt < 8; nt++) {
                mx0 = fmaxf(mx0, fmaxf(s[nt][0], s[nt][1]));
                mx1 = fmaxf(mx1, fmaxf(s[nt][2], s[nt][3]));
            }
            mx0 = fmaxf(mx0, __shfl_xor_sync(~0u, mx0, 1));
            mx0 = fmaxf(mx0, __shfl_xor_sync(~0u, mx0, 2));
            mx1 = fmaxf(mx1, __shfl_xor_sync(~0u, mx1, 1));
            mx1 = fmaxf(mx1, __shfl_xor_sync(~0u, mx1, 2));
            float mn0 = fmaxf(m0, mx0), mn1 = fmaxf(m1, mx1);
            float sc0 = __expf(m0 - mn0), sc1 = __expf(m1 - mn1);
            m0 = mn0; m1 = mn1;
            uint32_t pa[8], pb[8];
            float ls0 = 0.f, ls1 = 0.f;
            #pragma unroll
            for (int nt = 0; nt < 8; nt++) {
                float p0 = __expf(s[nt][0] - mn0), p1 = __expf(s[nt][1] - mn0);
                float p2 = __expf(s[nt][2] - mn1), p3 = __expf(s[nt][3] - mn1);
                ls0 += p0 + p1; ls1 += p2 + p3;
                pa[nt] = packh2(p0, p1);
                pb[nt] = packh2(p2, p3);
            }
            ls0 += __shfl_xor_sync(~0u, ls0, 1); ls0 += __shfl_xor_sync(~0u, ls0, 2);
            ls1 += __shfl_xor_sync(~0u, ls1, 1); ls1 += __shfl_xor_sync(~0u, ls1, 2);
            l0 = l0 * sc0 + ls0; l1 = l1 * sc1 + ls1;
            #pragma unroll
            for (int nt = 0; nt < 8; nt++) {
                o[nt][0] *= sc0; o[nt][1] *= sc0; o[nt][2] *= sc1; o[nt][3] *= sc1;
            }
            // O += P @ V
            #pragma unroll
            for (int ks = 0; ks < 4; ks++) {
                uint32_t af[4] = { pa[2 * ks], pb[2 * ks], pa[2 * ks + 1], pb[2 * ks + 1] };
                #pragma unroll
                for (int np = 0; np < 4; np++) {
                    int vrow = ks * 16 + (sub & 1) * 8 + lr;
                    int vcol = np * 16 + (sub >> 1) * 8;
                    uint32_t addr = vB[bf] + (vrow * FS + vcol) * 2;
                    uint32_t b0, b1, b2, b3;
                    ldsm_x4_trans(b0, b1, b2, b3, addr);
                    uint32_t bf0[2] = { b0, b1 }, bf1[2] = { b2, b3 };
                    mma_f16(o[2 * np], af, bf0);
                    mma_f16(o[2 * np + 1], af, bf1);
                }
            }
            __syncthreads();
        }

        float inv0 = 1.f / l0, inv1 = 1.f / l1;
        __half* O0 = O + (size_t)(b * T + qrow) * D + h * HD;
        __half* O1 = O0 + (size_t)8 * D;
        #pragma unroll
        for (int nt = 0; nt < 8; nt++) {
            int c = nt * 8 + 2 * qd;
            *(__half2*)(O0 + c) = __floats2half2_rn(o[nt][0] * inv0, o[nt][1] * inv0);
            *(__half2*)(O1 + c) = __floats2half2_rn(o[nt][2] * inv1, o[nt][3] * inv1);
        }
    }
}

// ======================= LayerNorm (fp32 in, fp16 out) =======================
__device__ __forceinline__ float block_sum256(float v, float* red) {
    int t = threadIdx.x;
    #pragma unroll
    for (int o = 16; o > 0; o >>= 1) v += __shfl_xor_sync(0xffffffffu, v, o);
    if ((t & 31) == 0) red[t >> 5] = v;
    __syncthreads();
    if (t < 32) {
        float s = (t < 8) ? red[t] : 0.0f;
        #pragma unroll
        for (int o = 4; o > 0; o >>= 1) s += __shfl_xor_sync(0xffffffffu, s, o);
        if (t == 0) red[0] = s;
    }
    __syncthreads();
    float r = red[0];
    __syncthreads();
    return r;
}

__global__ __launch_bounds__(256) void ln_kernel(
    const float* __restrict__ x, const float* __restrict__ g,
    const float* __restrict__ b, __half* __restrict__ out)
{
    __shared__ float red[32];
    int r = blockIdx.x, t = threadIdx.x;
    const float* xr = x + (size_t)r * D;
    float4 v = *(const float4*)(xr + t * 4);
    float mu = block_sum256(v.x + v.y + v.z + v.w, red) * (1.0f / D);
    float dx = v.x - mu, dy = v.y - mu, dz = v.z - mu, dw = v.w - mu;
    float var = block_sum256(dx * dx + dy * dy + dz * dz + dw * dw, red) * (1.0f / D);
    float inv = rsqrtf(var + 1e-5f);
    float4 gv = *(const float4*)(g + t * 4);
    float4 bv = *(const float4*)(b + t * 4);
    __half2 o01 = __floats2half2_rn(dx * inv * gv.x + bv.x, dy * inv * gv.y + bv.y);
    __half2 o23 = __floats2half2_rn(dz * inv * gv.z + bv.z, dw * inv * gv.w + bv.w);
    uint2 pk = make_uint2(*(uint32_t*)&o01, *(uint32_t*)&o23);
    *(uint2*)(out + (size_t)r * D + t * 4) = pk;
}

// ======================= launch =======================
template<typename Tp>
static Tp* sym_addr(const void* sym) {
    void* p = nullptr;
    cudaGetSymbolAddress(&p, sym);
    return (Tp*)p;
}

extern "C" void kernel_launch(void* const* d_in, const int* in_sizes, int n_in,
                              void* d_out, int out_size)
{
    const float* x     = (const float*)d_in[0];
    const float* w_qkv = (const float*)d_in[1];
    const float* b_qkv = (const float*)d_in[2];
    const float* w_fc  = (const float*)d_in[3];
    const float* b_fc  = (const float*)d_in[4];
    const float* ln1_g = (const float*)d_in[5];
    const float* ln1_b = (const float*)d_in[6];
    const float* ln2_g = (const float*)d_in[7];
    const float* ln2_b = (const float*)d_in[8];
    const float* w1    = (const float*)d_in[9];
    const float* b1    = (const float*)d_in[10];
    const float* w2    = (const float*)d_in[11];
    const float* b2    = (const float*)d_in[12];
    float* out = (float*)d_out;

    __half* p_h16  = sym_addr<__half>(g_h16);
    __half* p_qkv  = sym_addr<__half>(g_qkv16);
    __half* p_attn = sym_addr<__half>(g_attn16);
    float*  p_x1   = sym_addr<float>(g_x1);
    __half* p_h216 = sym_addr<__half>(g_h216);
    __half* p_ffn  = sym_addr<__half>(g_ffn16);
    __half* p_wqkv = sym_addr<__half>(g_wqkv16);
    __half* p_wfc  = sym_addr<__half>(g_wfc16);
    __half* p_w1   = sym_addr<__half>(g_w116);
    __half* p_w2   = sym_addr<__half>(g_w216);

    cudaFuncSetAttribute(gemm_h<false, false>, cudaFuncAttributeMaxDynamicSharedMemorySize, GEMM_SMEM);
    cudaFuncSetAttribute(gemm_h<false, true>,  cudaFuncAttributeMaxDynamicSharedMemorySize, GEMM_SMEM);
    cudaFuncSetAttribute(gemm_h<true,  false>, cudaFuncAttributeMaxDynamicSharedMemorySize, GEMM_SMEM);
    cudaFuncSetAttribute(flash_h, cudaFuncAttributeMaxDynamicSharedMemorySize, FA_SMEM_B);

    // fused weight converts (compile-time ranges)
    convert_all<<<CVT_TILES, 256>>>(
        w_qkv, p_wqkv, w_fc, p_wfc, w1, p_w1, w2, p_w2);

    // 1. h = LN1(x)  (fp16)
    ln_kernel<<<ROWS, 256>>>(x, ln1_g, ln1_b, p_h16);
    // 2. qkv = h @ w_qkv + b_qkv  (fp16 out)
    gemm_h<false, false><<<dim3(3 * D / 128, ROWS / 128), 256, GEMM_SMEM>>>(
        p_h16, p_wqkv, b_qkv, nullptr, nullptr, p_qkv, ROWS, 3 * D, D);
    // 3. fused attention (256 thr, q-tile 128, paired)
    flash_h<<<dim3(T / 256, BHCNT), 256, FA_SMEM_B>>>(p_qkv, p_attn);
    // 4. x1 = x + attn @ w_fc + b_fc  (fp32)
    gemm_h<false, true><<<dim3(D / 128, ROWS / 128), 256, GEMM_SMEM>>>(
        p_attn, p_wfc, b_fc, x, p_x1, nullptr, ROWS, D, D);
    // 5. h2 = LN2(x1)  (fp16)
    ln_kernel<<<ROWS, 256>>>(p_x1, ln2_g, ln2_b, p_h216);
    // 6. ffn = gelu(h2 @ w1 + b1)  (fp16)
    gemm_h<true, false><<<dim3(4 * D / 128, ROWS / 128), 256, GEMM_SMEM>>>(
        p_h216, p_w1, b1, nullptr, nullptr, p_ffn, ROWS, 4 * D, D);
    // 7. out = x1 + ffn @ w2 + b2  (fp32)
    gemm_h<false, true><<<dim3(D / 128, ROWS / 128), 256, GEMM_SMEM>>>(
        p_ffn, p_w2, b2, p_x1, out, nullptr, ROWS, D, 4 * D);
}